// round 2
// baseline (speedup 1.0000x reference)
#include <cuda_runtime.h>

// Problem constants
#define BB     4
#define NQ     1024
#define NK     2048
#define DIMT   1024
#define NH     16
#define DH     64
#define ROWS_Q (BB*NQ)                  // 4096
#define ROWS_K (BB*NK)                  // 8192
#define ROWS_TOT (ROWS_Q + 2*ROWS_K)    // 20480

typedef unsigned long long u64;

// Scratch (static device arrays: allocation-free per harness rules)
__device__ float g_ln[(size_t)ROWS_TOT * DIMT];   // LayerNorm'd q|k|v rows
__device__ float g_f [(size_t)ROWS_TOT * DIMT];   // projected features
__device__ float g_S [BB*NH*DH*DH];               // per-(b,h) 64x64  k_hat^T @ f_v
__device__ float g_attn[(size_t)ROWS_Q * DIMT];   // q_hat @ S, merged heads

// ---------------------------------------------------------------------------
// Packed f32x2 helpers (sm_100+/sm_103a): one fma-pipe slot, two fp32 FMAs.
// ---------------------------------------------------------------------------
__device__ __forceinline__ u64 fma2(u64 a, u64 b, u64 c) {
    u64 d;
    asm("fma.rn.f32x2 %0, %1, %2, %3;" : "=l"(d) : "l"(a), "l"(b), "l"(c));
    return d;
}
__device__ __forceinline__ u64 add2(u64 a, u64 b) {
    u64 d;
    asm("add.rn.f32x2 %0, %1, %2;" : "=l"(d) : "l"(a), "l"(b));
    return d;
}
__device__ __forceinline__ u64 pack2(float lo, float hi) {
    u64 d;
    asm("mov.b64 %0, {%1, %2};" : "=l"(d) : "f"(lo), "f"(hi));
    return d;
}

// ---------------------------------------------------------------------------
// Kernel 1: LayerNorm all q/k/v rows into one contiguous buffer.
// ---------------------------------------------------------------------------
__global__ void __launch_bounds__(256) ln_kernel(
    const float* __restrict__ q, const float* __restrict__ k,
    const float* __restrict__ v, const float* __restrict__ gamma,
    const float* __restrict__ beta)
{
    int row = blockIdx.x;
    const float* src;
    if (row < ROWS_Q)               src = q + (size_t)row * DIMT;
    else if (row < ROWS_Q + ROWS_K) src = k + (size_t)(row - ROWS_Q) * DIMT;
    else                            src = v + (size_t)(row - ROWS_Q - ROWS_K) * DIMT;
    float* dst = g_ln + (size_t)row * DIMT;

    int t = threadIdx.x;
    float4 x = reinterpret_cast<const float4*>(src)[t];
    float s  = x.x + x.y + x.z + x.w;
    float ss = x.x*x.x + x.y*x.y + x.z*x.z + x.w*x.w;
    #pragma unroll
    for (int o = 16; o > 0; o >>= 1) {
        s  += __shfl_xor_sync(0xffffffffu, s,  o);
        ss += __shfl_xor_sync(0xffffffffu, ss, o);
    }
    __shared__ float ws[8], wss[8];
    int wid = t >> 5, lane = t & 31;
    if (lane == 0) { ws[wid] = s; wss[wid] = ss; }
    __syncthreads();
    float tot = 0.f, totss = 0.f;
    #pragma unroll
    for (int i = 0; i < 8; i++) { tot += ws[i]; totss += wss[i]; }
    float mu  = tot * (1.0f / DIMT);
    float var = totss * (1.0f / DIMT) - mu * mu;       // biased, matches ref
    float rs  = rsqrtf(var + 1e-5f);

    float4 g  = reinterpret_cast<const float4*>(gamma)[t];
    float4 be = reinterpret_cast<const float4*>(beta)[t];
    float4 y;
    y.x = (x.x - mu) * rs * g.x + be.x;
    y.y = (x.y - mu) * rs * g.y + be.y;
    y.z = (x.z - mu) * rs * g.z + be.z;
    y.w = (x.w - mu) * rs * g.w + be.w;
    reinterpret_cast<float4*>(dst)[t] = y;
}

// ---------------------------------------------------------------------------
// Kernel 2: SGEMM via packed fma.rn.f32x2.
// C[M,N] = A[M,K] @ B[K,N] (+ bias[N]).
// 128x128 tile, BK=8, 256 threads, 8 rows x 8 cols per thread.
// A is staged DUPLICATED in smem ((a,a) pairs) so replicated-a operands come
// straight out of LDS.128 with no PACK instructions in the hot loop.
// acc packed along columns: acc[i][jp] = (C[i][2jp], C[i][2jp+1]).
// ---------------------------------------------------------------------------
__global__ void __launch_bounds__(256, 2) sgemm128(
    const float* __restrict__ A, const float* __restrict__ Bm,
    float* __restrict__ C, int M, int N, int K,
    const float* __restrict__ bias)
{
    __shared__ float As[8][256];   // duplicated: As[kk][2r] == As[kk][2r+1] == a(row r)
    __shared__ float Bs[8][128];
    const int t    = threadIdx.x;
    const int brow = blockIdx.y, bcol = blockIdx.x;
    const int trow = t >> 4, tcol = t & 15;

    u64 acc[8][4];
    #pragma unroll
    for (int i = 0; i < 8; i++)
        #pragma unroll
        for (int j = 0; j < 4; j++) acc[i][j] = 0ull;

    const int aRow = t >> 1;
    const int aCol = (t & 1) << 2;
    const int bRow = t >> 5;
    const int bCol = (t & 31) << 2;
    const float* Ap = A  + (size_t)(brow * 128 + aRow) * K + aCol;
    const float* Bp = Bm + (size_t)bRow * N + bcol * 128 + bCol;

    for (int k0 = 0; k0 < K; k0 += 8) {
        float4 a4 = *reinterpret_cast<const float4*>(Ap + k0);
        *reinterpret_cast<float2*>(&As[aCol + 0][2 * aRow]) = make_float2(a4.x, a4.x);
        *reinterpret_cast<float2*>(&As[aCol + 1][2 * aRow]) = make_float2(a4.y, a4.y);
        *reinterpret_cast<float2*>(&As[aCol + 2][2 * aRow]) = make_float2(a4.z, a4.z);
        *reinterpret_cast<float2*>(&As[aCol + 3][2 * aRow]) = make_float2(a4.w, a4.w);
        *reinterpret_cast<float4*>(&Bs[bRow][bCol]) =
            *reinterpret_cast<const float4*>(Bp + (size_t)k0 * N);
        __syncthreads();
        #pragma unroll
        for (int kk = 0; kk < 8; kk++) {
            // 8 replicated-a operands: (a_i, a_i) packed, from duplicated As
            ulonglong2 aq0 = *reinterpret_cast<const ulonglong2*>(&As[kk][trow * 16 + 0]);
            ulonglong2 aq1 = *reinterpret_cast<const ulonglong2*>(&As[kk][trow * 16 + 4]);
            ulonglong2 aq2 = *reinterpret_cast<const ulonglong2*>(&As[kk][trow * 16 + 8]);
            ulonglong2 aq3 = *reinterpret_cast<const ulonglong2*>(&As[kk][trow * 16 + 12]);
            u64 ar[8] = { aq0.x, aq0.y, aq1.x, aq1.y, aq2.x, aq2.y, aq3.x, aq3.y };
            // 4 natural b pairs: (b_{2j}, b_{2j+1})
            ulonglong2 bq0 = *reinterpret_cast<const ulonglong2*>(&Bs[kk][tcol * 8 + 0]);
            ulonglong2 bq1 = *reinterpret_cast<const ulonglong2*>(&Bs[kk][tcol * 8 + 4]);
            u64 br[4] = { bq0.x, bq0.y, bq1.x, bq1.y };
            #pragma unroll
            for (int i = 0; i < 8; i++) {
                #pragma unroll
                for (int j = 0; j < 4; j++)
                    acc[i][j] = fma2(ar[i], br[j], acc[i][j]);
            }
        }
        __syncthreads();
    }

    // bias packed as pairs (0 if no bias)
    u64 bp[4];
    #pragma unroll
    for (int j = 0; j < 4; j++) {
        if (bias) {
            const float* bb = bias + bcol * 128 + tcol * 8 + 2 * j;
            bp[j] = pack2(bb[0], bb[1]);
        } else {
            bp[j] = 0ull;
        }
    }

    #pragma unroll
    for (int i = 0; i < 8; i++) {
        int row = brow * 128 + trow * 8 + i;
        float* Crow = C + (size_t)row * N + bcol * 128 + tcol * 8;
        u64 o0 = add2(acc[i][0], bp[0]);
        u64 o1 = add2(acc[i][1], bp[1]);
        u64 o2 = add2(acc[i][2], bp[2]);
        u64 o3 = add2(acc[i][3], bp[3]);
        *reinterpret_cast<ulonglong2*>(Crow)     = make_ulonglong2(o0, o1);
        *reinterpret_cast<ulonglong2*>(Crow + 4) = make_ulonglong2(o2, o3);
    }
}

// ---------------------------------------------------------------------------
// Kernel 3: per (b,h):  S = k_hat^T @ f_v   (64x64), summing over m=2048.
// ---------------------------------------------------------------------------
__global__ void __launch_bounds__(256) kv_kernel()
{
    const int bh = blockIdx.x;
    const int b = bh >> 4, h = bh & 15;
    __shared__ float sk[32][64];
    __shared__ float sv[32][64];
    __shared__ float rkn[32];
    const int t = threadIdx.x;
    const int j1_0 = (t >> 4) << 2;
    const int j2_0 = (t & 15) << 2;
    const float* fk = g_f + (size_t)(ROWS_Q + b * NK) * DIMT + h * DH;
    const float* fv = g_f + (size_t)(ROWS_Q + ROWS_K + b * NK) * DIMT + h * DH;

    float acc[4][4];
    #pragma unroll
    for (int i = 0; i < 4; i++)
        #pragma unroll
        for (int j = 0; j < 4; j++) acc[i][j] = 0.f;

    for (int m0 = 0; m0 < NK; m0 += 32) {
        #pragma unroll
        for (int l = 0; l < 2; l++) {
            int idx = t + l * 256;               // 512 float4s per tensor
            int r = idx >> 4, c = (idx & 15) << 2;
            float4 kv4 = *reinterpret_cast<const float4*>(&fk[(size_t)(m0 + r) * DIMT + c]);
            float4 vv4 = *reinterpret_cast<const float4*>(&fv[(size_t)(m0 + r) * DIMT + c]);
            *reinterpret_cast<float4*>(&sk[r][c]) = kv4;
            *reinterpret_cast<float4*>(&sv[r][c]) = vv4;
            float s = kv4.x*kv4.x + kv4.y*kv4.y + kv4.z*kv4.z + kv4.w*kv4.w;
            #pragma unroll
            for (int o = 8; o > 0; o >>= 1) s += __shfl_xor_sync(0xffffffffu, s, o);
            if ((t & 15) == 0) rkn[r] = rsqrtf(s);
        }
        __syncthreads();
        #pragma unroll 8
        for (int m = 0; m < 32; m++) {
            float rk = rkn[m];
            float4 a  = *reinterpret_cast<float4*>(&sk[m][j1_0]);
            float4 bq = *reinterpret_cast<float4*>(&sv[m][j2_0]);
            float a0 = a.x * rk, a1 = a.y * rk, a2 = a.z * rk, a3 = a.w * rk;
            acc[0][0] = fmaf(a0, bq.x, acc[0][0]); acc[0][1] = fmaf(a0, bq.y, acc[0][1]);
            acc[0][2] = fmaf(a0, bq.z, acc[0][2]); acc[0][3] = fmaf(a0, bq.w, acc[0][3]);
            acc[1][0] = fmaf(a1, bq.x, acc[1][0]); acc[1][1] = fmaf(a1, bq.y, acc[1][1]);
            acc[1][2] = fmaf(a1, bq.z, acc[1][2]); acc[1][3] = fmaf(a1, bq.w, acc[1][3]);
            acc[2][0] = fmaf(a2, bq.x, acc[2][0]); acc[2][1] = fmaf(a2, bq.y, acc[2][1]);
            acc[2][2] = fmaf(a2, bq.z, acc[2][2]); acc[2][3] = fmaf(a2, bq.w, acc[2][3]);
            acc[3][0] = fmaf(a3, bq.x, acc[3][0]); acc[3][1] = fmaf(a3, bq.y, acc[3][1]);
            acc[3][2] = fmaf(a3, bq.z, acc[3][2]); acc[3][3] = fmaf(a3, bq.w, acc[3][3]);
        }
        __syncthreads();
    }
    float* Sp = g_S + (size_t)bh * (DH * DH);
    #pragma unroll
    for (int i = 0; i < 4; i++)
        *reinterpret_cast<float4*>(&Sp[(j1_0 + i) * DH + j2_0]) =
            make_float4(acc[i][0], acc[i][1], acc[i][2], acc[i][3]);
}

// ---------------------------------------------------------------------------
// Kernel 4: out_attn[row, h*64+j2] = (f_q_row/|f_q_row|) @ S[b,h]
// ---------------------------------------------------------------------------
__global__ void __launch_bounds__(256) qs_kernel()
{
    const int bh = blockIdx.y;
    const int nt = blockIdx.x;            // 16 tiles of 64 rows
    const int b = bh >> 4, h = bh & 15;
    __shared__ float sS[64][64];
    __shared__ float sqT[64][64];         // [j1][row]
    __shared__ float rqn[64];
    const int t = threadIdx.x;

    const float* Sp = g_S + (size_t)bh * (DH * DH);
    #pragma unroll
    for (int l = 0; l < 4; l++) {
        int idx = t + l * 256;
        reinterpret_cast<float4*>(sS)[idx] = reinterpret_cast<const float4*>(Sp)[idx];
    }
    const float* fq = g_f + (size_t)(b * NQ + nt * 64) * DIMT + h * DH;
    #pragma unroll
    for (int l = 0; l < 4; l++) {
        int idx = t + l * 256;
        int r = idx >> 4, c = (idx & 15) << 2;
        float4 x = *reinterpret_cast<const float4*>(&fq[(size_t)r * DIMT + c]);
        sqT[c + 0][r] = x.x; sqT[c + 1][r] = x.y;
        sqT[c + 2][r] = x.z; sqT[c + 3][r] = x.w;
        float s = x.x*x.x + x.y*x.y + x.z*x.z + x.w*x.w;
        #pragma unroll
        for (int o = 8; o > 0; o >>= 1) s += __shfl_xor_sync(0xffffffffu, s, o);
        if ((t & 15) == 0) rqn[r] = rsqrtf(s);
    }
    __syncthreads();

    float acc[4][4];
    #pragma unroll
    for (int i = 0; i < 4; i++)
        #pragma unroll
        for (int j = 0; j < 4; j++) acc[i][j] = 0.f;
    const int r0 = (t >> 4) << 2, c0 = (t & 15) << 2;
    #pragma unroll 8
    for (int j1 = 0; j1 < 64; j1++) {
        float4 a  = *reinterpret_cast<float4*>(&sqT[j1][r0]);
        float4 bq = *reinterpret_cast<float4*>(&sS[j1][c0]);
        acc[0][0] = fmaf(a.x, bq.x, acc[0][0]); acc[0][1] = fmaf(a.x, bq.y, acc[0][1]);
        acc[0][2] = fmaf(a.x, bq.z, acc[0][2]); acc[0][3] = fmaf(a.x, bq.w, acc[0][3]);
        acc[1][0] = fmaf(a.y, bq.x, acc[1][0]); acc[1][1] = fmaf(a.y, bq.y, acc[1][1]);
        acc[1][2] = fmaf(a.y, bq.z, acc[1][2]); acc[1][3] = fmaf(a.y, bq.w, acc[1][3]);
        acc[2][0] = fmaf(a.z, bq.x, acc[2][0]); acc[2][1] = fmaf(a.z, bq.y, acc[2][1]);
        acc[2][2] = fmaf(a.z, bq.z, acc[2][2]); acc[2][3] = fmaf(a.z, bq.w, acc[2][3]);
        acc[3][0] = fmaf(a.w, bq.x, acc[3][0]); acc[3][1] = fmaf(a.w, bq.y, acc[3][1]);
        acc[3][2] = fmaf(a.w, bq.z, acc[3][2]); acc[3][3] = fmaf(a.w, bq.w, acc[3][3]);
    }
    float* outp = g_attn + (size_t)(b * NQ + nt * 64 + r0) * DIMT + h * DH + c0;
    #pragma unroll
    for (int i = 0; i < 4; i++) {
        float rq = rqn[r0 + i];
        *reinterpret_cast<float4*>(outp + (size_t)i * DIMT) =
            make_float4(acc[i][0] * rq, acc[i][1] * rq, acc[i][2] * rq, acc[i][3] * rq);
    }
}

// ---------------------------------------------------------------------------
extern "C" void kernel_launch(void* const* d_in, const int* in_sizes, int n_in,
                              void* d_out, int out_size)
{
    const float* q     = (const float*)d_in[0];
    const float* k     = (const float*)d_in[1];
    const float* v     = (const float*)d_in[2];
    const float* gamma = (const float*)d_in[3];
    const float* beta  = (const float*)d_in[4];
    const float* W_in  = (const float*)d_in[5];
    const float* W_out = (const float*)d_in[6];
    const float* b_out = (const float*)d_in[7];
    float* out = (float*)d_out;

    float *p_ln, *p_f, *p_attn;
    cudaGetSymbolAddress((void**)&p_ln,   g_ln);
    cudaGetSymbolAddress((void**)&p_f,    g_f);
    cudaGetSymbolAddress((void**)&p_attn, g_attn);

    // 1) LayerNorm q|k|v
    ln_kernel<<<ROWS_TOT, 256>>>(q, k, v, gamma, beta);
    // 2) fused projection GEMM: f = LN(x) @ W_in   (20480 x 1024 x 1024)
    sgemm128<<<dim3(DIMT / 128, ROWS_TOT / 128), 256>>>(p_ln, W_in, p_f,
                                                        ROWS_TOT, DIMT, DIMT, nullptr);
    // 3) per-(b,h) S = k_hat^T @ f_v  (64x64 each)
    kv_kernel<<<BB * NH, 256>>>();
    // 4) attn_out = q_hat @ S, heads merged
    qs_kernel<<<dim3(NQ / 64, BB * NH), 256>>>();
    // 5) final GEMM + bias: out = attn_out @ W_out + b_out  (4096 x 1024 x 1024)
    sgemm128<<<dim3(DIMT / 128, ROWS_Q / 128), 256>>>(p_attn, W_out, out,
                                                      ROWS_Q, DIMT, DIMT, b_out);
}

// round 4
// speedup vs baseline: 2.4034x; 2.4034x over previous
#include <cuda_runtime.h>
#include <cuda_bf16.h>
#include <cstdint>

// Problem constants
#define BB     4
#define NQ     1024
#define NK     2048
#define DIMT   1024
#define NH     16
#define DH     64
#define ROWS_Q (BB*NQ)                  // 4096
#define ROWS_K (BB*NK)                  // 8192
#define ROWS_TOT (ROWS_Q + 2*ROWS_K)    // 20480

// Scratch (static device arrays: allocation-free per harness rules)
__device__ __nv_bfloat16 g_ah[(size_t)ROWS_TOT * DIMT];  // LN out, hi bf16
__device__ __nv_bfloat16 g_al[(size_t)ROWS_TOT * DIMT];  // LN out, lo bf16
__device__ float         g_f [(size_t)ROWS_TOT * DIMT];  // projected features (fp32)
__device__ float         g_S [BB*NH*DH*DH];              // per-(b,h) 64x64 k_hat^T @ f_v
__device__ __nv_bfloat16 g_oh[(size_t)ROWS_Q * DIMT];    // attn out, hi bf16
__device__ __nv_bfloat16 g_ol[(size_t)ROWS_Q * DIMT];    // attn out, lo bf16
__device__ __nv_bfloat16 g_wih[DIMT*DIMT], g_wil[DIMT*DIMT];  // W_in^T  hi/lo [N,K]
__device__ __nv_bfloat16 g_woh[DIMT*DIMT], g_wol[DIMT*DIMT];  // W_out^T hi/lo [N,K]

// ---------------------------------------------------------------------------
// Helpers
// ---------------------------------------------------------------------------
__device__ __forceinline__ uint32_t smem_u32(const void* p) {
    uint32_t a;
    asm("{ .reg .u64 t; cvta.to.shared.u64 t, %1; cvt.u32.u64 %0, t; }" : "=r"(a) : "l"(p));
    return a;
}
__device__ __forceinline__ void cp16(uint32_t saddr, const void* g) {
    asm volatile("cp.async.cg.shared.global [%0], [%1], 16;" :: "r"(saddr), "l"(g));
}
#define CP_COMMIT() asm volatile("cp.async.commit_group;" ::: "memory")
#define CP_WAIT(n)  asm volatile("cp.async.wait_group %0;" :: "n"(n) : "memory")

__device__ __forceinline__ void ldsm_x4(uint32_t* r, uint32_t addr) {
    asm volatile("ldmatrix.sync.aligned.m8n8.x4.shared.b16 {%0,%1,%2,%3}, [%4];"
                 : "=r"(r[0]), "=r"(r[1]), "=r"(r[2]), "=r"(r[3]) : "r"(addr));
}
__device__ __forceinline__ void ldsm_x2(uint32_t* r, uint32_t addr) {
    asm volatile("ldmatrix.sync.aligned.m8n8.x2.shared.b16 {%0,%1}, [%2];"
                 : "=r"(r[0]), "=r"(r[1]) : "r"(addr));
}
__device__ __forceinline__ void mma16816(float* c, const uint32_t* a, const uint32_t* b) {
    asm volatile("mma.sync.aligned.m16n8k16.row.col.f32.bf16.bf16.f32 "
                 "{%0,%1,%2,%3}, {%4,%5,%6,%7}, {%8,%9}, {%0,%1,%2,%3};"
                 : "+f"(c[0]), "+f"(c[1]), "+f"(c[2]), "+f"(c[3])
                 : "r"(a[0]), "r"(a[1]), "r"(a[2]), "r"(a[3]), "r"(b[0]), "r"(b[1]));
}
__device__ __forceinline__ void split2(float x, __nv_bfloat16& h, __nv_bfloat16& l) {
    h = __float2bfloat16_rn(x);
    l = __float2bfloat16_rn(x - __bfloat162float(h));
}

// ---------------------------------------------------------------------------
// Kernel 1: LayerNorm all q/k/v rows -> bf16 hi/lo split buffers.
// ---------------------------------------------------------------------------
__global__ void __launch_bounds__(256) ln_kernel(
    const float* __restrict__ q, const float* __restrict__ k,
    const float* __restrict__ v, const float* __restrict__ gamma,
    const float* __restrict__ beta)
{
    int row = blockIdx.x;
    const float* src;
    if (row < ROWS_Q)               src = q + (size_t)row * DIMT;
    else if (row < ROWS_Q + ROWS_K) src = k + (size_t)(row - ROWS_Q) * DIMT;
    else                            src = v + (size_t)(row - ROWS_Q - ROWS_K) * DIMT;

    int t = threadIdx.x;
    float4 x = reinterpret_cast<const float4*>(src)[t];
    float s  = x.x + x.y + x.z + x.w;
    float ss = x.x*x.x + x.y*x.y + x.z*x.z + x.w*x.w;
    #pragma unroll
    for (int o = 16; o > 0; o >>= 1) {
        s  += __shfl_xor_sync(0xffffffffu, s,  o);
        ss += __shfl_xor_sync(0xffffffffu, ss, o);
    }
    __shared__ float ws[8], wss[8];
    int wid = t >> 5, lane = t & 31;
    if (lane == 0) { ws[wid] = s; wss[wid] = ss; }
    __syncthreads();
    float tot = 0.f, totss = 0.f;
    #pragma unroll
    for (int i = 0; i < 8; i++) { tot += ws[i]; totss += wss[i]; }
    float mu  = tot * (1.0f / DIMT);
    float var = totss * (1.0f / DIMT) - mu * mu;       // biased, matches ref
    float rs  = rsqrtf(var + 1e-5f);

    float4 g  = reinterpret_cast<const float4*>(gamma)[t];
    float4 be = reinterpret_cast<const float4*>(beta)[t];
    float y0 = (x.x - mu) * rs * g.x + be.x;
    float y1 = (x.y - mu) * rs * g.y + be.y;
    float y2 = (x.z - mu) * rs * g.z + be.z;
    float y3 = (x.w - mu) * rs * g.w + be.w;

    __nv_bfloat16 h0, h1, h2, h3, l0, l1, l2, l3;
    split2(y0, h0, l0); split2(y1, h1, l1); split2(y2, h2, l2); split2(y3, h3, l3);
    ushort4 uh = make_ushort4(__bfloat16_as_ushort(h0), __bfloat16_as_ushort(h1),
                              __bfloat16_as_ushort(h2), __bfloat16_as_ushort(h3));
    ushort4 ul = make_ushort4(__bfloat16_as_ushort(l0), __bfloat16_as_ushort(l1),
                              __bfloat16_as_ushort(l2), __bfloat16_as_ushort(l3));
    reinterpret_cast<ushort4*>(g_ah + (size_t)row * DIMT)[t] = uh;
    reinterpret_cast<ushort4*>(g_al + (size_t)row * DIMT)[t] = ul;
}

// ---------------------------------------------------------------------------
// Kernel 1b: weight transpose + bf16 split.  W[K,N] row-major -> T_hi/lo[N,K].
// ---------------------------------------------------------------------------
__global__ void __launch_bounds__(256) wsplit_kernel(
    const float* __restrict__ W, __nv_bfloat16* __restrict__ Th,
    __nv_bfloat16* __restrict__ Tl, int K, int N)
{
    __shared__ float ts[32][33];
    int tx = threadIdx.x, ty = threadIdx.y;    // 32 x 8
    int k0 = blockIdx.y * 32, n0 = blockIdx.x * 32;
    #pragma unroll
    for (int j = 0; j < 4; j++)
        ts[ty + j * 8][tx] = W[(size_t)(k0 + ty + j * 8) * N + n0 + tx];
    __syncthreads();
    #pragma unroll
    for (int j = 0; j < 4; j++) {
        int n = n0 + ty + j * 8, k = k0 + tx;
        float x = ts[tx][ty + j * 8];
        __nv_bfloat16 h, l;
        split2(x, h, l);
        Th[(size_t)n * K + k] = h;
        Tl[(size_t)n * K + k] = l;
    }
}

// ---------------------------------------------------------------------------
// Kernel 2: mma.sync bf16x3 GEMM.  C[M,N] = A[M,K] @ Bt[N,K]^T (+bias).
// 128x128 tile, BK=32, 256 threads (8 warps, 2x4), warp tile 64x32.
// cp.async double-buffered smem; rows padded to 40 bf16 (80B) so ldmatrix's
// 8-row phases hit 8 distinct 16B banks (80*r mod 128 is an 8-cycle).
// 3 passes per k16: Ah*Bh + Ah*Bl + Al*Bh, fp32 accum (drop Al*Bl ~ 2^-18).
// ---------------------------------------------------------------------------
#define BKG     32
#define PADROW  40
#define TILE_B  (128 * PADROW * 2)     // 10240 B per tensor tile
#define STAGE_B (4 * TILE_B)           // 40960 B per stage
#define GSMEM   (2 * STAGE_B)          // 81920 B total

__global__ void __launch_bounds__(256) gemm_mma_bf16x3(
    const __nv_bfloat16* __restrict__ Ah, const __nv_bfloat16* __restrict__ Al,
    const __nv_bfloat16* __restrict__ Bh, const __nv_bfloat16* __restrict__ Bl,
    float* __restrict__ C, int M, int N, int K, const float* __restrict__ bias)
{
    extern __shared__ char sm[];
    const uint32_t sbase = smem_u32(sm);
    const int tid = threadIdx.x;
    const int lane = tid & 31;
    const int wid = tid >> 5;
    const int warp_m = wid >> 2;        // 0..1
    const int warp_n = wid & 3;         // 0..3
    const int brow = blockIdx.y, bcol = blockIdx.x;

    const __nv_bfloat16* tp[4] = {
        Ah + (size_t)brow * 128 * K, Al + (size_t)brow * 128 * K,
        Bh + (size_t)bcol * 128 * K, Bl + (size_t)bcol * 128 * K };

    // per-thread fixed load mapping: 8 chunks of 16B
    int l_tens[8], l_row[8], l_ch[8];
    #pragma unroll
    for (int l = 0; l < 8; l++) {
        int id = l * 256 + tid;
        l_tens[l] = id >> 9;
        int u = id & 511;
        l_row[l] = u >> 2;
        l_ch[l] = u & 3;
    }

    float acc[4][4][4];
    #pragma unroll
    for (int i = 0; i < 4; i++)
        #pragma unroll
        for (int j = 0; j < 4; j++)
            #pragma unroll
            for (int c = 0; c < 4; c++) acc[i][j][c] = 0.f;

    const int NS = K / BKG;             // 32 stages of K
    // prologue: stage 0
    #pragma unroll
    for (int l = 0; l < 8; l++) {
        uint32_t sa = sbase + l_tens[l] * TILE_B + l_row[l] * (PADROW * 2) + l_ch[l] * 16;
        cp16(sa, tp[l_tens[l]] + (size_t)l_row[l] * K + l_ch[l] * 8);
    }
    CP_COMMIT();

    for (int ks = 0; ks < NS; ks++) {
        if (ks + 1 < NS) {
            const int st = (ks + 1) & 1;
            const int k0 = (ks + 1) * BKG;
            #pragma unroll
            for (int l = 0; l < 8; l++) {
                uint32_t sa = sbase + st * STAGE_B + l_tens[l] * TILE_B
                            + l_row[l] * (PADROW * 2) + l_ch[l] * 16;
                cp16(sa, tp[l_tens[l]] + (size_t)l_row[l] * K + k0 + l_ch[l] * 8);
            }
            CP_COMMIT();
            CP_WAIT(1);
        } else {
            CP_WAIT(0);
        }
        __syncthreads();

        const uint32_t stb = sbase + (ks & 1) * STAGE_B;
        #pragma unroll
        for (int kk = 0; kk < 2; kk++) {          // two k16 halves of BK=32
            const int k0 = kk * 16;
            // B fragments for this warp's 4 n-tiles (hi & lo)
            uint32_t bh[4][2], bl[4][2];
            const int bn = warp_n * 32;
            const uint32_t bkoff = (uint32_t)((k0 + ((lane >> 3) & 1) * 8) * 2);
            #pragma unroll
            for (int nt = 0; nt < 4; nt++) {
                uint32_t roff = (uint32_t)(bn + nt * 8 + (lane & 7)) * (PADROW * 2);
                ldsm_x2(bh[nt], stb + 2 * TILE_B + roff + bkoff);
                ldsm_x2(bl[nt], stb + 3 * TILE_B + roff + bkoff);
            }
            const uint32_t akoff = (uint32_t)((k0 + (lane >> 4) * 8) * 2);
            #pragma unroll
            for (int mt = 0; mt < 4; mt++) {
                uint32_t ah4[4], al4[4];
                uint32_t roff = (uint32_t)(warp_m * 64 + mt * 16 + (lane & 15)) * (PADROW * 2);
                ldsm_x4(ah4, stb + roff + akoff);
                ldsm_x4(al4, stb + TILE_B + roff + akoff);
                #pragma unroll
                for (int nt = 0; nt < 4; nt++) {
                    mma16816(acc[mt][nt], ah4, bh[nt]);
                    mma16816(acc[mt][nt], ah4, bl[nt]);
                    mma16816(acc[mt][nt], al4, bh[nt]);
                }
            }
        }
        __syncthreads();
    }

    // epilogue
    #pragma unroll
    for (int mt = 0; mt < 4; mt++) {
        const int row0 = brow * 128 + warp_m * 64 + mt * 16 + (lane >> 2);
        #pragma unroll
        for (int nt = 0; nt < 4; nt++) {
            const int col = bcol * 128 + warp_n * 32 + nt * 8 + (lane & 3) * 2;
            float b0 = 0.f, b1 = 0.f;
            if (bias) { b0 = __ldg(&bias[col]); b1 = __ldg(&bias[col + 1]); }
            *reinterpret_cast<float2*>(C + (size_t)row0 * N + col) =
                make_float2(acc[mt][nt][0] + b0, acc[mt][nt][1] + b1);
            *reinterpret_cast<float2*>(C + (size_t)(row0 + 8) * N + col) =
                make_float2(acc[mt][nt][2] + b0, acc[mt][nt][3] + b1);
        }
    }
}

// ---------------------------------------------------------------------------
// Kernel 3: per (b,h):  S = k_hat^T @ f_v   (64x64), summing over m=2048.
// ---------------------------------------------------------------------------
__global__ void __launch_bounds__(256) kv_kernel()
{
    const int bh = blockIdx.x;
    const int b = bh >> 4, h = bh & 15;
    __shared__ float sk[32][64];
    __shared__ float sv[32][64];
    __shared__ float rkn[32];
    const int t = threadIdx.x;
    const int j1_0 = (t >> 4) << 2;
    const int j2_0 = (t & 15) << 2;
    const float* fk = g_f + (size_t)(ROWS_Q + b * NK) * DIMT + h * DH;
    const float* fv = g_f + (size_t)(ROWS_Q + ROWS_K + b * NK) * DIMT + h * DH;

    float acc[4][4];
    #pragma unroll
    for (int i = 0; i < 4; i++)
        #pragma unroll
        for (int j = 0; j < 4; j++) acc[i][j] = 0.f;

    for (int m0 = 0; m0 < NK; m0 += 32) {
        #pragma unroll
        for (int l = 0; l < 2; l++) {
            int idx = t + l * 256;
            int r = idx >> 4, c = (idx & 15) << 2;
            float4 kv4 = *reinterpret_cast<const float4*>(&fk[(size_t)(m0 + r) * DIMT + c]);
            float4 vv4 = *reinterpret_cast<const float4*>(&fv[(size_t)(m0 + r) * DIMT + c]);
            *reinterpret_cast<float4*>(&sk[r][c]) = kv4;
            *reinterpret_cast<float4*>(&sv[r][c]) = vv4;
            float s = kv4.x*kv4.x + kv4.y*kv4.y + kv4.z*kv4.z + kv4.w*kv4.w;
            #pragma unroll
            for (int o = 8; o > 0; o >>= 1) s += __shfl_xor_sync(0xffffffffu, s, o);
            if ((t & 15) == 0) rkn[r] = rsqrtf(s);
        }
        __syncthreads();
        #pragma unroll 8
        for (int m = 0; m < 32; m++) {
            float rk = rkn[m];
            float4 a  = *reinterpret_cast<float4*>(&sk[m][j1_0]);
            float4 bq = *reinterpret_cast<float4*>(&sv[m][j2_0]);
            float a0 = a.x * rk, a1 = a.y * rk, a2 = a.z * rk, a3 = a.w * rk;
            acc[0][0] = fmaf(a0, bq.x, acc[0][0]); acc[0][1] = fmaf(a0, bq.y, acc[0][1]);
            acc[0][2] = fmaf(a0, bq.z, acc[0][2]); acc[0][3] = fmaf(a0, bq.w, acc[0][3]);
            acc[1][0] = fmaf(a1, bq.x, acc[1][0]); acc[1][1] = fmaf(a1, bq.y, acc[1][1]);
            acc[1][2] = fmaf(a1, bq.z, acc[1][2]); acc[1][3] = fmaf(a1, bq.w, acc[1][3]);
            acc[2][0] = fmaf(a2, bq.x, acc[2][0]); acc[2][1] = fmaf(a2, bq.y, acc[2][1]);
            acc[2][2] = fmaf(a2, bq.z, acc[2][2]); acc[2][3] = fmaf(a2, bq.w, acc[2][3]);
            acc[3][0] = fmaf(a3, bq.x, acc[3][0]); acc[3][1] = fmaf(a3, bq.y, acc[3][1]);
            acc[3][2] = fmaf(a3, bq.z, acc[3][2]); acc[3][3] = fmaf(a3, bq.w, acc[3][3]);
        }
        __syncthreads();
    }
    float* Sp = g_S + (size_t)bh * (DH * DH);
    #pragma unroll
    for (int i = 0; i < 4; i++)
        *reinterpret_cast<float4*>(&Sp[(j1_0 + i) * DH + j2_0]) =
            make_float4(acc[i][0], acc[i][1], acc[i][2], acc[i][3]);
}

// ---------------------------------------------------------------------------
// Kernel 4: out_attn = (f_q/|f_q|) @ S[b,h]  -> bf16 hi/lo split, heads merged.
// ---------------------------------------------------------------------------
__global__ void __launch_bounds__(256) qs_kernel()
{
    const int bh = blockIdx.y;
    const int nt = blockIdx.x;
    const int b = bh >> 4, h = bh & 15;
    __shared__ float sS[64][64];
    __shared__ float sqT[64][64];
    __shared__ float rqn[64];
    const int t = threadIdx.x;

    const float* Sp = g_S + (size_t)bh * (DH * DH);
    #pragma unroll
    for (int l = 0; l < 4; l++) {
        int idx = t + l * 256;
        reinterpret_cast<float4*>(sS)[idx] = reinterpret_cast<const float4*>(Sp)[idx];
    }
    const float* fq = g_f + (size_t)(b * NQ + nt * 64) * DIMT + h * DH;
    #pragma unroll
    for (int l = 0; l < 4; l++) {
        int idx = t + l * 256;
        int r = idx >> 4, c = (idx & 15) << 2;
        float4 x = *reinterpret_cast<const float4*>(&fq[(size_t)r * DIMT + c]);
        sqT[c + 0][r] = x.x; sqT[c + 1][r] = x.y;
        sqT[c + 2][r] = x.z; sqT[c + 3][r] = x.w;
        float s = x.x*x.x + x.y*x.y + x.z*x.z + x.w*x.w;
        #pragma unroll
        for (int o = 8; o > 0; o >>= 1) s += __shfl_xor_sync(0xffffffffu, s, o);
        if ((t & 15) == 0) rqn[r] = rsqrtf(s);
    }
    __syncthreads();

    float acc[4][4];
    #pragma unroll
    for (int i = 0; i < 4; i++)
        #pragma unroll
        for (int j = 0; j < 4; j++) acc[i][j] = 0.f;
    const int r0 = (t >> 4) << 2, c0 = (t & 15) << 2;
    #pragma unroll 8
    for (int j1 = 0; j1 < 64; j1++) {
        float4 a  = *reinterpret_cast<float4*>(&sqT[j1][r0]);
        float4 bq = *reinterpret_cast<float4*>(&sS[j1][c0]);
        acc[0][0] = fmaf(a.x, bq.x, acc[0][0]); acc[0][1] = fmaf(a.x, bq.y, acc[0][1]);
        acc[0][2] = fmaf(a.x, bq.z, acc[0][2]); acc[0][3] = fmaf(a.x, bq.w, acc[0][3]);
        acc[1][0] = fmaf(a.y, bq.x, acc[1][0]); acc[1][1] = fmaf(a.y, bq.y, acc[1][1]);
        acc[1][2] = fmaf(a.y, bq.z, acc[1][2]); acc[1][3] = fmaf(a.y, bq.w, acc[1][3]);
        acc[2][0] = fmaf(a.z, bq.x, acc[2][0]); acc[2][1] = fmaf(a.z, bq.y, acc[2][1]);
        acc[2][2] = fmaf(a.z, bq.z, acc[2][2]); acc[2][3] = fmaf(a.z, bq.w, acc[2][3]);
        acc[3][0] = fmaf(a.w, bq.x, acc[3][0]); acc[3][1] = fmaf(a.w, bq.y, acc[3][1]);
        acc[3][2] = fmaf(a.w, bq.z, acc[3][2]); acc[3][3] = fmaf(a.w, bq.w, acc[3][3]);
    }
    const size_t obase = (size_t)(b * NQ + nt * 64 + r0) * DIMT + h * DH + c0;
    #pragma unroll
    for (int i = 0; i < 4; i++) {
        float rq = rqn[r0 + i];
        __nv_bfloat16 h0, h1, h2, h3, l0, l1, l2, l3;
        split2(acc[i][0] * rq, h0, l0); split2(acc[i][1] * rq, h1, l1);
        split2(acc[i][2] * rq, h2, l2); split2(acc[i][3] * rq, h3, l3);
        ushort4 uh = make_ushort4(__bfloat16_as_ushort(h0), __bfloat16_as_ushort(h1),
                                  __bfloat16_as_ushort(h2), __bfloat16_as_ushort(h3));
        ushort4 ul = make_ushort4(__bfloat16_as_ushort(l0), __bfloat16_as_ushort(l1),
                                  __bfloat16_as_ushort(l2), __bfloat16_as_ushort(l3));
        *reinterpret_cast<ushort4*>(g_oh + obase + (size_t)i * DIMT) = uh;
        *reinterpret_cast<ushort4*>(g_ol + obase + (size_t)i * DIMT) = ul;
    }
}

// ---------------------------------------------------------------------------
extern "C" void kernel_launch(void* const* d_in, const int* in_sizes, int n_in,
                              void* d_out, int out_size)
{
    const float* q     = (const float*)d_in[0];
    const float* k     = (const float*)d_in[1];
    const float* v     = (const float*)d_in[2];
    const float* gamma = (const float*)d_in[3];
    const float* beta  = (const float*)d_in[4];
    const float* W_in  = (const float*)d_in[5];
    const float* W_out = (const float*)d_in[6];
    const float* b_out = (const float*)d_in[7];
    float* out = (float*)d_out;

    __nv_bfloat16 *p_ah, *p_al, *p_oh, *p_ol, *p_wih, *p_wil, *p_woh, *p_wol;
    float *p_f;
    cudaGetSymbolAddress((void**)&p_ah,  g_ah);
    cudaGetSymbolAddress((void**)&p_al,  g_al);
    cudaGetSymbolAddress((void**)&p_oh,  g_oh);
    cudaGetSymbolAddress((void**)&p_ol,  g_ol);
    cudaGetSymbolAddress((void**)&p_wih, g_wih);
    cudaGetSymbolAddress((void**)&p_wil, g_wil);
    cudaGetSymbolAddress((void**)&p_woh, g_woh);
    cudaGetSymbolAddress((void**)&p_wol, g_wol);
    cudaGetSymbolAddress((void**)&p_f,   g_f);

    cudaFuncSetAttribute(gemm_mma_bf16x3,
                         cudaFuncAttributeMaxDynamicSharedMemorySize, GSMEM);

    // 0) weight transpose + bf16 split
    wsplit_kernel<<<dim3(32, 32), dim3(32, 8)>>>(W_in,  p_wih, p_wil, DIMT, DIMT);
    wsplit_kernel<<<dim3(32, 32), dim3(32, 8)>>>(W_out, p_woh, p_wol, DIMT, DIMT);
    // 1) LayerNorm q|k|v -> bf16 hi/lo
    ln_kernel<<<ROWS_TOT, 256>>>(q, k, v, gamma, beta);
    // 2) projection GEMM (tensor cores): f = LN(x) @ W_in
    gemm_mma_bf16x3<<<dim3(DIMT / 128, ROWS_TOT / 128), 256, GSMEM>>>(
        p_ah, p_al, p_wih, p_wil, p_f, ROWS_TOT, DIMT, DIMT, nullptr);
    // 3) per-(b,h) S = k_hat^T @ f_v
    kv_kernel<<<BB * NH, 256>>>();
    // 4) attn = q_hat @ S -> bf16 hi/lo
    qs_kernel<<<dim3(NQ / 64, BB * NH), 256>>>();
    // 5) output GEMM (tensor cores): out = attn @ W_out + b_out
    gemm_mma_bf16x3<<<dim3(DIMT / 128, ROWS_Q / 128), 256, GSMEM>>>(
        p_oh, p_ol, p_woh, p_wol, out, ROWS_Q, DIMT, DIMT, b_out);
}

// round 5
// speedup vs baseline: 2.6352x; 1.0964x over previous
#include <cuda_runtime.h>
#include <cuda_bf16.h>
#include <cstdint>

// Problem constants
#define BB     4
#define NQ     1024
#define NK     2048
#define DIMT   1024
#define NH     16
#define DH     64
#define ROWS_Q (BB*NQ)                  // 4096
#define ROWS_K (BB*NK)                  // 8192
#define ROWS_TOT (ROWS_Q + 2*ROWS_K)    // 20480

// Scratch (static device arrays: allocation-free per harness rules)
__device__ __nv_bfloat16 g_ah[(size_t)ROWS_TOT * DIMT];  // LN out, hi bf16
__device__ __nv_bfloat16 g_al[(size_t)ROWS_TOT * DIMT];  // LN out, lo bf16
__device__ float         g_f [(size_t)ROWS_TOT * DIMT];  // projected features (fp32)
__device__ float         g_S [BB*NH*DH*DH];              // per-(b,h) 64x64 k_hat^T @ f_v
__device__ __nv_bfloat16 g_oh[(size_t)ROWS_Q * DIMT];    // attn out, hi bf16
__device__ __nv_bfloat16 g_ol[(size_t)ROWS_Q * DIMT];    // attn out, lo bf16
__device__ __nv_bfloat16 g_wih[DIMT*DIMT], g_wil[DIMT*DIMT];  // W_in^T  hi/lo [N,K]
__device__ __nv_bfloat16 g_woh[DIMT*DIMT], g_wol[DIMT*DIMT];  // W_out^T hi/lo [N,K]

// ---------------------------------------------------------------------------
// Helpers
// ---------------------------------------------------------------------------
__device__ __forceinline__ uint32_t smem_u32(const void* p) {
    uint32_t a;
    asm("{ .reg .u64 t; cvta.to.shared.u64 t, %1; cvt.u32.u64 %0, t; }" : "=r"(a) : "l"(p));
    return a;
}
__device__ __forceinline__ void cp16(uint32_t saddr, const void* g) {
    asm volatile("cp.async.cg.shared.global [%0], [%1], 16;" :: "r"(saddr), "l"(g));
}
#define CP_COMMIT() asm volatile("cp.async.commit_group;" ::: "memory")
#define CP_WAIT(n)  asm volatile("cp.async.wait_group %0;" :: "n"(n) : "memory")

__device__ __forceinline__ void ldsm_x4(uint32_t* r, uint32_t addr) {
    asm volatile("ldmatrix.sync.aligned.m8n8.x4.shared.b16 {%0,%1,%2,%3}, [%4];"
                 : "=r"(r[0]), "=r"(r[1]), "=r"(r[2]), "=r"(r[3]) : "r"(addr));
}
__device__ __forceinline__ void ldsm_x2(uint32_t* r, uint32_t addr) {
    asm volatile("ldmatrix.sync.aligned.m8n8.x2.shared.b16 {%0,%1}, [%2];"
                 : "=r"(r[0]), "=r"(r[1]) : "r"(addr));
}
__device__ __forceinline__ void mma16816(float* c, const uint32_t* a, const uint32_t* b) {
    asm volatile("mma.sync.aligned.m16n8k16.row.col.f32.bf16.bf16.f32 "
                 "{%0,%1,%2,%3}, {%4,%5,%6,%7}, {%8,%9}, {%0,%1,%2,%3};"
                 : "+f"(c[0]), "+f"(c[1]), "+f"(c[2]), "+f"(c[3])
                 : "r"(a[0]), "r"(a[1]), "r"(a[2]), "r"(a[3]), "r"(b[0]), "r"(b[1]));
}
__device__ __forceinline__ void split2(float x, __nv_bfloat16& h, __nv_bfloat16& l) {
    h = __float2bfloat16_rn(x);
    l = __float2bfloat16_rn(x - __bfloat162float(h));
}

// ---------------------------------------------------------------------------
// Kernel 1: LayerNorm all q/k/v rows -> bf16 hi/lo split buffers.
// ---------------------------------------------------------------------------
__global__ void __launch_bounds__(256) ln_kernel(
    const float* __restrict__ q, const float* __restrict__ k,
    const float* __restrict__ v, const float* __restrict__ gamma,
    const float* __restrict__ beta)
{
    int row = blockIdx.x;
    const float* src;
    if (row < ROWS_Q)               src = q + (size_t)row * DIMT;
    else if (row < ROWS_Q + ROWS_K) src = k + (size_t)(row - ROWS_Q) * DIMT;
    else                            src = v + (size_t)(row - ROWS_Q - ROWS_K) * DIMT;

    int t = threadIdx.x;
    float4 x = reinterpret_cast<const float4*>(src)[t];
    float s  = x.x + x.y + x.z + x.w;
    float ss = x.x*x.x + x.y*x.y + x.z*x.z + x.w*x.w;
    #pragma unroll
    for (int o = 16; o > 0; o >>= 1) {
        s  += __shfl_xor_sync(0xffffffffu, s,  o);
        ss += __shfl_xor_sync(0xffffffffu, ss, o);
    }
    __shared__ float ws[8], wss[8];
    int wid = t >> 5, lane = t & 31;
    if (lane == 0) { ws[wid] = s; wss[wid] = ss; }
    __syncthreads();
    float tot = 0.f, totss = 0.f;
    #pragma unroll
    for (int i = 0; i < 8; i++) { tot += ws[i]; totss += wss[i]; }
    float mu  = tot * (1.0f / DIMT);
    float var = totss * (1.0f / DIMT) - mu * mu;       // biased, matches ref
    float rs  = rsqrtf(var + 1e-5f);

    float4 g  = reinterpret_cast<const float4*>(gamma)[t];
    float4 be = reinterpret_cast<const float4*>(beta)[t];
    float y0 = (x.x - mu) * rs * g.x + be.x;
    float y1 = (x.y - mu) * rs * g.y + be.y;
    float y2 = (x.z - mu) * rs * g.z + be.z;
    float y3 = (x.w - mu) * rs * g.w + be.w;

    __nv_bfloat16 h0, h1, h2, h3, l0, l1, l2, l3;
    split2(y0, h0, l0); split2(y1, h1, l1); split2(y2, h2, l2); split2(y3, h3, l3);
    ushort4 uh = make_ushort4(__bfloat16_as_ushort(h0), __bfloat16_as_ushort(h1),
                              __bfloat16_as_ushort(h2), __bfloat16_as_ushort(h3));
    ushort4 ul = make_ushort4(__bfloat16_as_ushort(l0), __bfloat16_as_ushort(l1),
                              __bfloat16_as_ushort(l2), __bfloat16_as_ushort(l3));
    reinterpret_cast<ushort4*>(g_ah + (size_t)row * DIMT)[t] = uh;
    reinterpret_cast<ushort4*>(g_al + (size_t)row * DIMT)[t] = ul;
}

// ---------------------------------------------------------------------------
// Kernel 1b: weight transpose + bf16 split.  W[K,N] row-major -> T_hi/lo[N,K].
// ---------------------------------------------------------------------------
__global__ void __launch_bounds__(256) wsplit_kernel(
    const float* __restrict__ W, __nv_bfloat16* __restrict__ Th,
    __nv_bfloat16* __restrict__ Tl, int K, int N)
{
    __shared__ float ts[32][33];
    int tx = threadIdx.x, ty = threadIdx.y;    // 32 x 8
    int k0 = blockIdx.y * 32, n0 = blockIdx.x * 32;
    #pragma unroll
    for (int j = 0; j < 4; j++)
        ts[ty + j * 8][tx] = W[(size_t)(k0 + ty + j * 8) * N + n0 + tx];
    __syncthreads();
    #pragma unroll
    for (int j = 0; j < 4; j++) {
        int n = n0 + ty + j * 8, k = k0 + tx;
        float x = ts[tx][ty + j * 8];
        __nv_bfloat16 h, l;
        split2(x, h, l);
        Th[(size_t)n * K + k] = h;
        Tl[(size_t)n * K + k] = l;
    }
}

// ---------------------------------------------------------------------------
// Kernel 2: mma.sync bf16x3 GEMM.  C[M,N] = A[M,K] @ Bt[N,K]^T (+bias).
// 128x128 tile, BK=32, 256 threads (8 warps, 2x4), warp tile 64x32.
// cp.async double-buffered smem; rows padded to 40 bf16 (80B) so ldmatrix's
// 8-row phases hit 8 distinct 16B banks (80*r mod 128 is an 8-cycle).
// 3 passes per k16: Ah*Bh + Ah*Bl + Al*Bh, fp32 accum (drop Al*Bl ~ 2^-18).
// __launch_bounds__(256, 2): clamp regs to 128 so 2 CTAs fit per SM
// (R4 measured 136 regs -> 1 CTA/SM -> occ 12.5%, tensor pipe 50% idle).
// ---------------------------------------------------------------------------
#define BKG     32
#define PADROW  40
#define TILE_B  (128 * PADROW * 2)     // 10240 B per tensor tile
#define STAGE_B (4 * TILE_B)           // 40960 B per stage
#define GSMEM   (2 * STAGE_B)          // 81920 B total

__global__ void __launch_bounds__(256, 2) gemm_mma_bf16x3(
    const __nv_bfloat16* __restrict__ Ah, const __nv_bfloat16* __restrict__ Al,
    const __nv_bfloat16* __restrict__ Bh, const __nv_bfloat16* __restrict__ Bl,
    float* __restrict__ C, int M, int N, int K, const float* __restrict__ bias)
{
    extern __shared__ char sm[];
    const uint32_t sbase = smem_u32(sm);
    const int tid = threadIdx.x;
    const int lane = tid & 31;
    const int wid = tid >> 5;
    const int warp_m = wid >> 2;        // 0..1
    const int warp_n = wid & 3;         // 0..3
    const int brow = blockIdx.y, bcol = blockIdx.x;

    const __nv_bfloat16* tp[4] = {
        Ah + (size_t)brow * 128 * K, Al + (size_t)brow * 128 * K,
        Bh + (size_t)bcol * 128 * K, Bl + (size_t)bcol * 128 * K };

    // per-thread fixed load mapping: 8 chunks of 16B
    int l_tens[8], l_row[8], l_ch[8];
    #pragma unroll
    for (int l = 0; l < 8; l++) {
        int id = l * 256 + tid;
        l_tens[l] = id >> 9;
        int u = id & 511;
        l_row[l] = u >> 2;
        l_ch[l] = u & 3;
    }

    float acc[4][4][4];
    #pragma unroll
    for (int i = 0; i < 4; i++)
        #pragma unroll
        for (int j = 0; j < 4; j++)
            #pragma unroll
            for (int c = 0; c < 4; c++) acc[i][j][c] = 0.f;

    const int NS = K / BKG;             // 32 stages of K
    // prologue: stage 0
    #pragma unroll
    for (int l = 0; l < 8; l++) {
        uint32_t sa = sbase + l_tens[l] * TILE_B + l_row[l] * (PADROW * 2) + l_ch[l] * 16;
        cp16(sa, tp[l_tens[l]] + (size_t)l_row[l] * K + l_ch[l] * 8);
    }
    CP_COMMIT();

    for (int ks = 0; ks < NS; ks++) {
        if (ks + 1 < NS) {
            const int st = (ks + 1) & 1;
            const int k0 = (ks + 1) * BKG;
            #pragma unroll
            for (int l = 0; l < 8; l++) {
                uint32_t sa = sbase + st * STAGE_B + l_tens[l] * TILE_B
                            + l_row[l] * (PADROW * 2) + l_ch[l] * 16;
                cp16(sa, tp[l_tens[l]] + (size_t)l_row[l] * K + k0 + l_ch[l] * 8);
            }
            CP_COMMIT();
            CP_WAIT(1);
        } else {
            CP_WAIT(0);
        }
        __syncthreads();

        const uint32_t stb = sbase + (ks & 1) * STAGE_B;
        #pragma unroll
        for (int kk = 0; kk < 2; kk++) {          // two k16 halves of BK=32
            const int k0 = kk * 16;
            // B fragments for this warp's 4 n-tiles (hi & lo)
            uint32_t bh[4][2], bl[4][2];
            const int bn = warp_n * 32;
            const uint32_t bkoff = (uint32_t)((k0 + ((lane >> 3) & 1) * 8) * 2);
            #pragma unroll
            for (int nt = 0; nt < 4; nt++) {
                uint32_t roff = (uint32_t)(bn + nt * 8 + (lane & 7)) * (PADROW * 2);
                ldsm_x2(bh[nt], stb + 2 * TILE_B + roff + bkoff);
                ldsm_x2(bl[nt], stb + 3 * TILE_B + roff + bkoff);
            }
            const uint32_t akoff = (uint32_t)((k0 + (lane >> 4) * 8) * 2);
            #pragma unroll
            for (int mt = 0; mt < 4; mt++) {
                uint32_t ah4[4], al4[4];
                uint32_t roff = (uint32_t)(warp_m * 64 + mt * 16 + (lane & 15)) * (PADROW * 2);
                ldsm_x4(ah4, stb + roff + akoff);
                ldsm_x4(al4, stb + TILE_B + roff + akoff);
                #pragma unroll
                for (int nt = 0; nt < 4; nt++) {
                    mma16816(acc[mt][nt], ah4, bh[nt]);
                    mma16816(acc[mt][nt], ah4, bl[nt]);
                    mma16816(acc[mt][nt], al4, bh[nt]);
                }
            }
        }
        __syncthreads();
    }

    // epilogue
    #pragma unroll
    for (int mt = 0; mt < 4; mt++) {
        const int row0 = brow * 128 + warp_m * 64 + mt * 16 + (lane >> 2);
        #pragma unroll
        for (int nt = 0; nt < 4; nt++) {
            const int col = bcol * 128 + warp_n * 32 + nt * 8 + (lane & 3) * 2;
            float b0 = 0.f, b1 = 0.f;
            if (bias) { b0 = __ldg(&bias[col]); b1 = __ldg(&bias[col + 1]); }
            *reinterpret_cast<float2*>(C + (size_t)row0 * N + col) =
                make_float2(acc[mt][nt][0] + b0, acc[mt][nt][1] + b1);
            *reinterpret_cast<float2*>(C + (size_t)(row0 + 8) * N + col) =
                make_float2(acc[mt][nt][2] + b0, acc[mt][nt][3] + b1);
        }
    }
}

// ---------------------------------------------------------------------------
// Kernel 3: per (b,h):  S = k_hat^T @ f_v   (64x64), summing over m=2048.
// ---------------------------------------------------------------------------
__global__ void __launch_bounds__(256) kv_kernel()
{
    const int bh = blockIdx.x;
    const int b = bh >> 4, h = bh & 15;
    __shared__ float sk[32][64];
    __shared__ float sv[32][64];
    __shared__ float rkn[32];
    const int t = threadIdx.x;
    const int j1_0 = (t >> 4) << 2;
    const int j2_0 = (t & 15) << 2;
    const float* fk = g_f + (size_t)(ROWS_Q + b * NK) * DIMT + h * DH;
    const float* fv = g_f + (size_t)(ROWS_Q + ROWS_K + b * NK) * DIMT + h * DH;

    float acc[4][4];
    #pragma unroll
    for (int i = 0; i < 4; i++)
        #pragma unroll
        for (int j = 0; j < 4; j++) acc[i][j] = 0.f;

    for (int m0 = 0; m0 < NK; m0 += 32) {
        #pragma unroll
        for (int l = 0; l < 2; l++) {
            int idx = t + l * 256;
            int r = idx >> 4, c = (idx & 15) << 2;
            float4 kv4 = *reinterpret_cast<const float4*>(&fk[(size_t)(m0 + r) * DIMT + c]);
            float4 vv4 = *reinterpret_cast<const float4*>(&fv[(size_t)(m0 + r) * DIMT + c]);
            *reinterpret_cast<float4*>(&sk[r][c]) = kv4;
            *reinterpret_cast<float4*>(&sv[r][c]) = vv4;
            float s = kv4.x*kv4.x + kv4.y*kv4.y + kv4.z*kv4.z + kv4.w*kv4.w;
            #pragma unroll
            for (int o = 8; o > 0; o >>= 1) s += __shfl_xor_sync(0xffffffffu, s, o);
            if ((t & 15) == 0) rkn[r] = rsqrtf(s);
        }
        __syncthreads();
        #pragma unroll 8
        for (int m = 0; m < 32; m++) {
            float rk = rkn[m];
            float4 a  = *reinterpret_cast<float4*>(&sk[m][j1_0]);
            float4 bq = *reinterpret_cast<float4*>(&sv[m][j2_0]);
            float a0 = a.x * rk, a1 = a.y * rk, a2 = a.z * rk, a3 = a.w * rk;
            acc[0][0] = fmaf(a0, bq.x, acc[0][0]); acc[0][1] = fmaf(a0, bq.y, acc[0][1]);
            acc[0][2] = fmaf(a0, bq.z, acc[0][2]); acc[0][3] = fmaf(a0, bq.w, acc[0][3]);
            acc[1][0] = fmaf(a1, bq.x, acc[1][0]); acc[1][1] = fmaf(a1, bq.y, acc[1][1]);
            acc[1][2] = fmaf(a1, bq.z, acc[1][2]); acc[1][3] = fmaf(a1, bq.w, acc[1][3]);
            acc[2][0] = fmaf(a2, bq.x, acc[2][0]); acc[2][1] = fmaf(a2, bq.y, acc[2][1]);
            acc[2][2] = fmaf(a2, bq.z, acc[2][2]); acc[2][3] = fmaf(a2, bq.w, acc[2][3]);
            acc[3][0] = fmaf(a3, bq.x, acc[3][0]); acc[3][1] = fmaf(a3, bq.y, acc[3][1]);
            acc[3][2] = fmaf(a3, bq.z, acc[3][2]); acc[3][3] = fmaf(a3, bq.w, acc[3][3]);
        }
        __syncthreads();
    }
    float* Sp = g_S + (size_t)bh * (DH * DH);
    #pragma unroll
    for (int i = 0; i < 4; i++)
        *reinterpret_cast<float4*>(&Sp[(j1_0 + i) * DH + j2_0]) =
            make_float4(acc[i][0], acc[i][1], acc[i][2], acc[i][3]);
}

// ---------------------------------------------------------------------------
// Kernel 4: out_attn = (f_q/|f_q|) @ S[b,h]  -> bf16 hi/lo split, heads merged.
// ---------------------------------------------------------------------------
__global__ void __launch_bounds__(256) qs_kernel()
{
    const int bh = blockIdx.y;
    const int nt = blockIdx.x;
    const int b = bh >> 4, h = bh & 15;
    __shared__ float sS[64][64];
    __shared__ float sqT[64][64];
    __shared__ float rqn[64];
    const int t = threadIdx.x;

    const float* Sp = g_S + (size_t)bh * (DH * DH);
    #pragma unroll
    for (int l = 0; l < 4; l++) {
        int idx = t + l * 256;
        reinterpret_cast<float4*>(sS)[idx] = reinterpret_cast<const float4*>(Sp)[idx];
    }
    const float* fq = g_f + (size_t)(b * NQ + nt * 64) * DIMT + h * DH;
    #pragma unroll
    for (int l = 0; l < 4; l++) {
        int idx = t + l * 256;
        int r = idx >> 4, c = (idx & 15) << 2;
        float4 x = *reinterpret_cast<const float4*>(&fq[(size_t)r * DIMT + c]);
        sqT[c + 0][r] = x.x; sqT[c + 1][r] = x.y;
        sqT[c + 2][r] = x.z; sqT[c + 3][r] = x.w;
        float s = x.x*x.x + x.y*x.y + x.z*x.z + x.w*x.w;
        #pragma unroll
        for (int o = 8; o > 0; o >>= 1) s += __shfl_xor_sync(0xffffffffu, s, o);
        if ((t & 15) == 0) rqn[r] = rsqrtf(s);
    }
    __syncthreads();

    float acc[4][4];
    #pragma unroll
    for (int i = 0; i < 4; i++)
        #pragma unroll
        for (int j = 0; j < 4; j++) acc[i][j] = 0.f;
    const int r0 = (t >> 4) << 2, c0 = (t & 15) << 2;
    #pragma unroll 8
    for (int j1 = 0; j1 < 64; j1++) {
        float4 a  = *reinterpret_cast<float4*>(&sqT[j1][r0]);
        float4 bq = *reinterpret_cast<float4*>(&sS[j1][c0]);
        acc[0][0] = fmaf(a.x, bq.x, acc[0][0]); acc[0][1] = fmaf(a.x, bq.y, acc[0][1]);
        acc[0][2] = fmaf(a.x, bq.z, acc[0][2]); acc[0][3] = fmaf(a.x, bq.w, acc[0][3]);
        acc[1][0] = fmaf(a.y, bq.x, acc[1][0]); acc[1][1] = fmaf(a.y, bq.y, acc[1][1]);
        acc[1][2] = fmaf(a.y, bq.z, acc[1][2]); acc[1][3] = fmaf(a.y, bq.w, acc[1][3]);
        acc[2][0] = fmaf(a.z, bq.x, acc[2][0]); acc[2][1] = fmaf(a.z, bq.y, acc[2][1]);
        acc[2][2] = fmaf(a.z, bq.z, acc[2][2]); acc[2][3] = fmaf(a.z, bq.w, acc[2][3]);
        acc[3][0] = fmaf(a.w, bq.x, acc[3][0]); acc[3][1] = fmaf(a.w, bq.y, acc[3][1]);
        acc[3][2] = fmaf(a.w, bq.z, acc[3][2]); acc[3][3] = fmaf(a.w, bq.w, acc[3][3]);
    }
    const size_t obase = (size_t)(b * NQ + nt * 64 + r0) * DIMT + h * DH + c0;
    #pragma unroll
    for (int i = 0; i < 4; i++) {
        float rq = rqn[r0 + i];
        __nv_bfloat16 h0, h1, h2, h3, l0, l1, l2, l3;
        split2(acc[i][0] * rq, h0, l0); split2(acc[i][1] * rq, h1, l1);
        split2(acc[i][2] * rq, h2, l2); split2(acc[i][3] * rq, h3, l3);
        ushort4 uh = make_ushort4(__bfloat16_as_ushort(h0), __bfloat16_as_ushort(h1),
                                  __bfloat16_as_ushort(h2), __bfloat16_as_ushort(h3));
        ushort4 ul = make_ushort4(__bfloat16_as_ushort(l0), __bfloat16_as_ushort(l1),
                                  __bfloat16_as_ushort(l2), __bfloat16_as_ushort(l3));
        *reinterpret_cast<ushort4*>(g_oh + obase + (size_t)i * DIMT) = uh;
        *reinterpret_cast<ushort4*>(g_ol + obase + (size_t)i * DIMT) = ul;
    }
}

// ---------------------------------------------------------------------------
extern "C" void kernel_launch(void* const* d_in, const int* in_sizes, int n_in,
                              void* d_out, int out_size)
{
    const float* q     = (const float*)d_in[0];
    const float* k     = (const float*)d_in[1];
    const float* v     = (const float*)d_in[2];
    const float* gamma = (const float*)d_in[3];
    const float* beta  = (const float*)d_in[4];
    const float* W_in  = (const float*)d_in[5];
    const float* W_out = (const float*)d_in[6];
    const float* b_out = (const float*)d_in[7];
    float* out = (float*)d_out;

    __nv_bfloat16 *p_ah, *p_al, *p_oh, *p_ol, *p_wih, *p_wil, *p_woh, *p_wol;
    float *p_f;
    cudaGetSymbolAddress((void**)&p_ah,  g_ah);
    cudaGetSymbolAddress((void**)&p_al,  g_al);
    cudaGetSymbolAddress((void**)&p_oh,  g_oh);
    cudaGetSymbolAddress((void**)&p_ol,  g_ol);
    cudaGetSymbolAddress((void**)&p_wih, g_wih);
    cudaGetSymbolAddress((void**)&p_wil, g_wil);
    cudaGetSymbolAddress((void**)&p_woh, g_woh);
    cudaGetSymbolAddress((void**)&p_wol, g_wol);
    cudaGetSymbolAddress((void**)&p_f,   g_f);

    cudaFuncSetAttribute(gemm_mma_bf16x3,
                         cudaFuncAttributeMaxDynamicSharedMemorySize, GSMEM);

    // 0) weight transpose + bf16 split
    wsplit_kernel<<<dim3(32, 32), dim3(32, 8)>>>(W_in,  p_wih, p_wil, DIMT, DIMT);
    wsplit_kernel<<<dim3(32, 32), dim3(32, 8)>>>(W_out, p_woh, p_wol, DIMT, DIMT);
    // 1) LayerNorm q|k|v -> bf16 hi/lo
    ln_kernel<<<ROWS_TOT, 256>>>(q, k, v, gamma, beta);
    // 2) projection GEMM (tensor cores): f = LN(x) @ W_in
    gemm_mma_bf16x3<<<dim3(DIMT / 128, ROWS_TOT / 128), 256, GSMEM>>>(
        p_ah, p_al, p_wih, p_wil, p_f, ROWS_TOT, DIMT, DIMT, nullptr);
    // 3) per-(b,h) S = k_hat^T @ f_v
    kv_kernel<<<BB * NH, 256>>>();
    // 4) attn = q_hat @ S -> bf16 hi/lo
    qs_kernel<<<dim3(NQ / 64, BB * NH), 256>>>();
    // 5) output GEMM (tensor cores): out = attn @ W_out + b_out
    gemm_mma_bf16x3<<<dim3(DIMT / 128, ROWS_Q / 128), 256, GSMEM>>>(
        p_oh, p_ol, p_woh, p_wol, out, ROWS_Q, DIMT, DIMT, b_out);
}

// round 7
// speedup vs baseline: 3.4737x; 1.3182x over previous
#include <cuda_runtime.h>
#include <cuda_bf16.h>
#include <cstdint>

// Problem constants
#define BB     4
#define NQ     1024
#define NK     2048
#define DIMT   1024
#define NH     16
#define DH     64
#define ROWS_Q (BB*NQ)                  // 4096
#define ROWS_K (BB*NK)                  // 8192
#define ROWS_TOT (ROWS_Q + 2*ROWS_K)    // 20480
#define KVPARTS 8

// Scratch (static device arrays: allocation-free per harness rules)
__device__ __nv_bfloat16 g_ah[(size_t)ROWS_TOT * DIMT];  // LN out, hi bf16
__device__ __nv_bfloat16 g_al[(size_t)ROWS_TOT * DIMT];  // LN out, lo bf16
__device__ float         g_f [(size_t)ROWS_TOT * DIMT];  // projected features (fp32)
__device__ float         g_S [BB*NH*DH*DH];              // per-(b,h) 64x64 k_hat^T @ f_v
__device__ float         g_Sp[KVPARTS*BB*NH*DH*DH];      // kv partial sums
__device__ __nv_bfloat16 g_oh[(size_t)ROWS_Q * DIMT];    // attn out, hi bf16
__device__ __nv_bfloat16 g_ol[(size_t)ROWS_Q * DIMT];    // attn out, lo bf16
__device__ __nv_bfloat16 g_wih[DIMT*DIMT], g_wil[DIMT*DIMT];  // W_in^T  hi/lo [N,K]
__device__ __nv_bfloat16 g_woh[DIMT*DIMT], g_wol[DIMT*DIMT];  // W_out^T hi/lo [N,K]

// ---------------------------------------------------------------------------
// Helpers
// ---------------------------------------------------------------------------
__device__ __forceinline__ uint32_t smem_u32(const void* p) {
    uint32_t a;
    asm("{ .reg .u64 t; cvta.to.shared.u64 t, %1; cvt.u32.u64 %0, t; }" : "=r"(a) : "l"(p));
    return a;
}
__device__ __forceinline__ void cp16(uint32_t saddr, const void* g) {
    asm volatile("cp.async.cg.shared.global [%0], [%1], 16;" :: "r"(saddr), "l"(g));
}
#define CP_COMMIT() asm volatile("cp.async.commit_group;" ::: "memory")
#define CP_WAIT(n)  asm volatile("cp.async.wait_group %0;" :: "n"(n) : "memory")

__device__ __forceinline__ void ldsm_x4(uint32_t* r, uint32_t addr) {
    asm volatile("ldmatrix.sync.aligned.m8n8.x4.shared.b16 {%0,%1,%2,%3}, [%4];"
                 : "=r"(r[0]), "=r"(r[1]), "=r"(r[2]), "=r"(r[3]) : "r"(addr));
}
__device__ __forceinline__ void mma16816(float* c, const uint32_t* a, const uint32_t* b) {
    asm volatile("mma.sync.aligned.m16n8k16.row.col.f32.bf16.bf16.f32 "
                 "{%0,%1,%2,%3}, {%4,%5,%6,%7}, {%8,%9}, {%0,%1,%2,%3};"
                 : "+f"(c[0]), "+f"(c[1]), "+f"(c[2]), "+f"(c[3])
                 : "r"(a[0]), "r"(a[1]), "r"(a[2]), "r"(a[3]), "r"(b[0]), "r"(b[1]));
}
__device__ __forceinline__ void split2(float x, __nv_bfloat16& h, __nv_bfloat16& l) {
    h = __float2bfloat16_rn(x);
    l = __float2bfloat16_rn(x - __bfloat162float(h));
}
// XOR chunk swizzle for 64B rows of 4x16B chunks: 16B-aligned, ldmatrix
// 8-row phases hit all 8 banks (see round theory for the bank proof).
__device__ __forceinline__ uint32_t sw_off(uint32_t row, uint32_t chunk) {
    return row * 64u + (chunk ^ ((row >> 1) & 3u)) * 16u;
}

// ---------------------------------------------------------------------------
// Kernel 1: LayerNorm all q/k/v rows -> bf16 hi/lo split buffers.
// ---------------------------------------------------------------------------
__global__ void __launch_bounds__(256) ln_kernel(
    const float* __restrict__ q, const float* __restrict__ k,
    const float* __restrict__ v, const float* __restrict__ gamma,
    const float* __restrict__ beta)
{
    int row = blockIdx.x;
    const float* src;
    if (row < ROWS_Q)               src = q + (size_t)row * DIMT;
    else if (row < ROWS_Q + ROWS_K) src = k + (size_t)(row - ROWS_Q) * DIMT;
    else                            src = v + (size_t)(row - ROWS_Q - ROWS_K) * DIMT;

    int t = threadIdx.x;
    float4 x = reinterpret_cast<const float4*>(src)[t];
    float s  = x.x + x.y + x.z + x.w;
    float ss = x.x*x.x + x.y*x.y + x.z*x.z + x.w*x.w;
    #pragma unroll
    for (int o = 16; o > 0; o >>= 1) {
        s  += __shfl_xor_sync(0xffffffffu, s,  o);
        ss += __shfl_xor_sync(0xffffffffu, ss, o);
    }
    __shared__ float ws[8], wss[8];
    int wid = t >> 5, lane = t & 31;
    if (lane == 0) { ws[wid] = s; wss[wid] = ss; }
    __syncthreads();
    float tot = 0.f, totss = 0.f;
    #pragma unroll
    for (int i = 0; i < 8; i++) { tot += ws[i]; totss += wss[i]; }
    float mu  = tot * (1.0f / DIMT);
    float var = totss * (1.0f / DIMT) - mu * mu;       // biased, matches ref
    float rs  = rsqrtf(var + 1e-5f);

    float4 g  = reinterpret_cast<const float4*>(gamma)[t];
    float4 be = reinterpret_cast<const float4*>(beta)[t];
    float y0 = (x.x - mu) * rs * g.x + be.x;
    float y1 = (x.y - mu) * rs * g.y + be.y;
    float y2 = (x.z - mu) * rs * g.z + be.z;
    float y3 = (x.w - mu) * rs * g.w + be.w;

    __nv_bfloat16 h0, h1, h2, h3, l0, l1, l2, l3;
    split2(y0, h0, l0); split2(y1, h1, l1); split2(y2, h2, l2); split2(y3, h3, l3);
    ushort4 uh = make_ushort4(__bfloat16_as_ushort(h0), __bfloat16_as_ushort(h1),
                              __bfloat16_as_ushort(h2), __bfloat16_as_ushort(h3));
    ushort4 ul = make_ushort4(__bfloat16_as_ushort(l0), __bfloat16_as_ushort(l1),
                              __bfloat16_as_ushort(l2), __bfloat16_as_ushort(l3));
    reinterpret_cast<ushort4*>(g_ah + (size_t)row * DIMT)[t] = uh;
    reinterpret_cast<ushort4*>(g_al + (size_t)row * DIMT)[t] = ul;
}

// ---------------------------------------------------------------------------
// Kernel 1b: weight transpose + bf16 split.  W[K,N] row-major -> T_hi/lo[N,K].
// ---------------------------------------------------------------------------
__global__ void __launch_bounds__(256) wsplit_kernel(
    const float* __restrict__ W, __nv_bfloat16* __restrict__ Th,
    __nv_bfloat16* __restrict__ Tl, int K, int N)
{
    __shared__ float ts[32][33];
    int tx = threadIdx.x, ty = threadIdx.y;    // 32 x 8
    int k0 = blockIdx.y * 32, n0 = blockIdx.x * 32;
    #pragma unroll
    for (int j = 0; j < 4; j++)
        ts[ty + j * 8][tx] = W[(size_t)(k0 + ty + j * 8) * N + n0 + tx];
    __syncthreads();
    #pragma unroll
    for (int j = 0; j < 4; j++) {
        int n = n0 + ty + j * 8, k = k0 + tx;
        float x = ts[tx][ty + j * 8];
        __nv_bfloat16 h, l;
        split2(x, h, l);
        Th[(size_t)n * K + k] = h;
        Tl[(size_t)n * K + k] = l;
    }
}

// ---------------------------------------------------------------------------
// Kernel 2: mma.sync bf16x3 GEMM.  C[M,N] = A[M,K] @ Bt[N,K]^T (+bias).
// 128x128 tile, BK=32, 256 threads (8 warps, 2x4), warp tile 64x32.
// 3-stage cp.async pipeline, ONE __syncthreads per slab (prefetch distance 2
// writes a stage whose last reader finished before this slab's sync).
// Tiles stored with 64B rows + XOR chunk swizzle (16B-aligned, conflict-free).
// 3 stages x 32KB = 96KB -> 2 CTAs/SM = 192KB + static < 228KB carveout.
// 3 passes per k16: Ah*Bh + Ah*Bl + Al*Bh, fp32 accum (drop Al*Bl ~ 2^-18).
// ---------------------------------------------------------------------------
#define BKG     32
#define ROWB    64                     // 64 B per row (32 bf16, unpadded)
#define TILE_B  (128 * ROWB)           // 8192 B per tensor tile
#define STAGE_B (4 * TILE_B)           // 32768 B per stage
#define GSMEM   (3 * STAGE_B)          // 98304 B total

__global__ void __launch_bounds__(256, 2) gemm_mma_bf16x3(
    const __nv_bfloat16* __restrict__ Ah, const __nv_bfloat16* __restrict__ Al,
    const __nv_bfloat16* __restrict__ Bh, const __nv_bfloat16* __restrict__ Bl,
    float* __restrict__ C, int M, int N, int K, const float* __restrict__ bias)
{
    extern __shared__ char sm[];
    const uint32_t sbase = smem_u32(sm);
    const int tid = threadIdx.x;
    const int lane = tid & 31;
    const int wid = tid >> 5;
    const int warp_m = wid >> 2;        // 0..1
    const int warp_n = wid & 3;         // 0..3
    const int brow = blockIdx.y, bcol = blockIdx.x;

    const __nv_bfloat16* tp[4] = {
        Ah + (size_t)brow * 128 * K, Al + (size_t)brow * 128 * K,
        Bh + (size_t)bcol * 128 * K, Bl + (size_t)bcol * 128 * K };

    // per-thread fixed load mapping: 8 chunks of 16B (2048 chunks / 256 thr)
    int l_tens[8], l_row[8], l_ch[8];
    #pragma unroll
    for (int l = 0; l < 8; l++) {
        int id = l * 256 + tid;
        l_tens[l] = id >> 9;
        int u = id & 511;
        l_row[l] = u >> 2;
        l_ch[l] = u & 3;
    }

    float acc[4][4][4];
    #pragma unroll
    for (int i = 0; i < 4; i++)
        #pragma unroll
        for (int j = 0; j < 4; j++)
            #pragma unroll
            for (int c = 0; c < 4; c++) acc[i][j][c] = 0.f;

    const int NS = K / BKG;             // 32 slabs

    // prologue: slabs 0 and 1
    #pragma unroll
    for (int pr = 0; pr < 2; pr++) {
        #pragma unroll
        for (int l = 0; l < 8; l++) {
            uint32_t sa = sbase + pr * STAGE_B + l_tens[l] * TILE_B
                        + sw_off((uint32_t)l_row[l], (uint32_t)l_ch[l]);
            cp16(sa, tp[l_tens[l]] + (size_t)l_row[l] * K + pr * BKG + l_ch[l] * 8);
        }
        CP_COMMIT();
    }

    // ldmatrix lane mappings (logical chunk = kk*2 + lane k-bit, swizzled per row)
    const int b_rowlane = ((lane >> 4) & 1) * 8 + (lane & 7);
    const uint32_t b_kbit = (uint32_t)((lane >> 3) & 1);
    const uint32_t a_kbit = (uint32_t)(lane >> 4);
    const int bn = warp_n * 32;

    for (int ks = 0; ks < NS; ks++) {
        if (ks + 2 < NS) CP_WAIT(1); else CP_WAIT(0);
        __syncthreads();

        // prefetch slab ks+2 into stage (ks+2)%3
        if (ks + 2 < NS) {
            const int st = (ks + 2) % 3;
            const int k0 = (ks + 2) * BKG;
            #pragma unroll
            for (int l = 0; l < 8; l++) {
                uint32_t sa = sbase + st * STAGE_B + l_tens[l] * TILE_B
                            + sw_off((uint32_t)l_row[l], (uint32_t)l_ch[l]);
                cp16(sa, tp[l_tens[l]] + (size_t)l_row[l] * K + k0 + l_ch[l] * 8);
            }
            CP_COMMIT();
        }

        const uint32_t stb = sbase + (ks % 3) * STAGE_B;
        #pragma unroll
        for (int kk = 0; kk < 2; kk++) {          // two k16 halves of BK=32
            const uint32_t bchunk = (uint32_t)(kk * 2) + b_kbit;
            const uint32_t achunk = (uint32_t)(kk * 2) + a_kbit;
            // B fragments: 2 ldsm_x4 per tensor cover 4 n-tiles x 2 k-halves
            uint32_t bh[4][2], bl[4][2];
            #pragma unroll
            for (int p = 0; p < 2; p++) {
                uint32_t brr = (uint32_t)(bn + p * 16 + b_rowlane);
                uint32_t boff = sw_off(brr, bchunk);
                uint32_t r4[4];
                ldsm_x4(r4, stb + 2 * TILE_B + boff);
                bh[2*p][0] = r4[0]; bh[2*p][1] = r4[1];
                bh[2*p+1][0] = r4[2]; bh[2*p+1][1] = r4[3];
                ldsm_x4(r4, stb + 3 * TILE_B + boff);
                bl[2*p][0] = r4[0]; bl[2*p][1] = r4[1];
                bl[2*p+1][0] = r4[2]; bl[2*p+1][1] = r4[3];
            }
            #pragma unroll
            for (int mt = 0; mt < 4; mt++) {
                uint32_t ah4[4], al4[4];
                uint32_t arr = (uint32_t)(warp_m * 64 + mt * 16 + (lane & 15));
                uint32_t aoff = sw_off(arr, achunk);
                ldsm_x4(ah4, stb + aoff);
                ldsm_x4(al4, stb + TILE_B + aoff);
                #pragma unroll
                for (int nt = 0; nt < 4; nt++) {
                    mma16816(acc[mt][nt], ah4, bh[nt]);
                    mma16816(acc[mt][nt], ah4, bl[nt]);
                    mma16816(acc[mt][nt], al4, bh[nt]);
                }
            }
        }
    }

    // epilogue
    #pragma unroll
    for (int mt = 0; mt < 4; mt++) {
        const int row0 = brow * 128 + warp_m * 64 + mt * 16 + (lane >> 2);
        #pragma unroll
        for (int nt = 0; nt < 4; nt++) {
            const int col = bcol * 128 + warp_n * 32 + nt * 8 + (lane & 3) * 2;
            float b0 = 0.f, b1 = 0.f;
            if (bias) { b0 = __ldg(&bias[col]); b1 = __ldg(&bias[col + 1]); }
            *reinterpret_cast<float2*>(C + (size_t)row0 * N + col) =
                make_float2(acc[mt][nt][0] + b0, acc[mt][nt][1] + b1);
            *reinterpret_cast<float2*>(C + (size_t)(row0 + 8) * N + col) =
                make_float2(acc[mt][nt][2] + b0, acc[mt][nt][3] + b1);
        }
    }
}

// ---------------------------------------------------------------------------
// Kernel 3: kv partials. Per (b,h,part): S_p = sum over its 256 m-rows of
// k_hat^T @ f_v.  grid = (64, KVPARTS) -> 512 CTAs (full-chip).
// ---------------------------------------------------------------------------
__global__ void __launch_bounds__(256) kv_part_kernel()
{
    const int bh = blockIdx.x;
    const int part = blockIdx.y;
    const int b = bh >> 4, h = bh & 15;
    __shared__ float sk[32][64];
    __shared__ float sv[32][64];
    __shared__ float rkn[32];
    const int t = threadIdx.x;
    const int j1_0 = (t >> 4) << 2;
    const int j2_0 = (t & 15) << 2;
    const int mbase = part * (NK / KVPARTS);
    const float* fk = g_f + (size_t)(ROWS_Q + b * NK + mbase) * DIMT + h * DH;
    const float* fv = g_f + (size_t)(ROWS_Q + ROWS_K + b * NK + mbase) * DIMT + h * DH;

    float acc[4][4];
    #pragma unroll
    for (int i = 0; i < 4; i++)
        #pragma unroll
        for (int j = 0; j < 4; j++) acc[i][j] = 0.f;

    for (int m0 = 0; m0 < NK / KVPARTS; m0 += 32) {
        #pragma unroll
        for (int l = 0; l < 2; l++) {
            int idx = t + l * 256;
            int r = idx >> 4, c = (idx & 15) << 2;
            float4 kv4 = *reinterpret_cast<const float4*>(&fk[(size_t)(m0 + r) * DIMT + c]);
            float4 vv4 = *reinterpret_cast<const float4*>(&fv[(size_t)(m0 + r) * DIMT + c]);
            *reinterpret_cast<float4*>(&sk[r][c]) = kv4;
            *reinterpret_cast<float4*>(&sv[r][c]) = vv4;
            float s = kv4.x*kv4.x + kv4.y*kv4.y + kv4.z*kv4.z + kv4.w*kv4.w;
            #pragma unroll
            for (int o = 8; o > 0; o >>= 1) s += __shfl_xor_sync(0xffffffffu, s, o);
            if ((t & 15) == 0) rkn[r] = rsqrtf(s);
        }
        __syncthreads();
        #pragma unroll 8
        for (int m = 0; m < 32; m++) {
            float rk = rkn[m];
            float4 a  = *reinterpret_cast<float4*>(&sk[m][j1_0]);
            float4 bq = *reinterpret_cast<float4*>(&sv[m][j2_0]);
            float a0 = a.x * rk, a1 = a.y * rk, a2 = a.z * rk, a3 = a.w * rk;
            acc[0][0] = fmaf(a0, bq.x, acc[0][0]); acc[0][1] = fmaf(a0, bq.y, acc[0][1]);
            acc[0][2] = fmaf(a0, bq.z, acc[0][2]); acc[0][3] = fmaf(a0, bq.w, acc[0][3]);
            acc[1][0] = fmaf(a1, bq.x, acc[1][0]); acc[1][1] = fmaf(a1, bq.y, acc[1][1]);
            acc[1][2] = fmaf(a1, bq.z, acc[1][2]); acc[1][3] = fmaf(a1, bq.w, acc[1][3]);
            acc[2][0] = fmaf(a2, bq.x, acc[2][0]); acc[2][1] = fmaf(a2, bq.y, acc[2][1]);
            acc[2][2] = fmaf(a2, bq.z, acc[2][2]); acc[2][3] = fmaf(a2, bq.w, acc[2][3]);
            acc[3][0] = fmaf(a3, bq.x, acc[3][0]); acc[3][1] = fmaf(a3, bq.y, acc[3][1]);
            acc[3][2] = fmaf(a3, bq.z, acc[3][2]); acc[3][3] = fmaf(a3, bq.w, acc[3][3]);
        }
        __syncthreads();
    }
    float* Sp = g_Sp + ((size_t)part * (BB * NH) + bh) * (DH * DH);
    #pragma unroll
    for (int i = 0; i < 4; i++)
        *reinterpret_cast<float4*>(&Sp[(j1_0 + i) * DH + j2_0]) =
            make_float4(acc[i][0], acc[i][1], acc[i][2], acc[i][3]);
}

// Reduce KVPARTS partials into g_S. grid=64, block=256; 4 float4 per thread.
__global__ void __launch_bounds__(256) s_reduce_kernel()
{
    const int bh = blockIdx.x;
    const int t = threadIdx.x;
    const size_t base = (size_t)bh * (DH * DH);
    #pragma unroll
    for (int l = 0; l < 4; l++) {
        int idx = t + l * 256;                       // 1024 float4s per matrix
        float4 s = make_float4(0.f, 0.f, 0.f, 0.f);
        #pragma unroll
        for (int p = 0; p < KVPARTS; p++) {
            float4 v = reinterpret_cast<const float4*>(
                g_Sp + ((size_t)p * (BB * NH)) * (DH * DH) + base)[idx];
            s.x += v.x; s.y += v.y; s.z += v.z; s.w += v.w;
        }
        reinterpret_cast<float4*>(g_S + base)[idx] = s;
    }
}

// ---------------------------------------------------------------------------
// Kernel 4: out_attn = (f_q/|f_q|) @ S[b,h]  -> bf16 hi/lo split, heads merged.
// ---------------------------------------------------------------------------
__global__ void __launch_bounds__(256) qs_kernel()
{
    const int bh = blockIdx.y;
    const int nt = blockIdx.x;
    const int b = bh >> 4, h = bh & 15;
    __shared__ float sS[64][64];
    __shared__ float sqT[64][64];
    __shared__ float rqn[64];
    const int t = threadIdx.x;

    const float* Sp = g_S + (size_t)bh * (DH * DH);
    #pragma unroll
    for (int l = 0; l < 4; l++) {
        int idx = t + l * 256;
        reinterpret_cast<float4*>(sS)[idx] = reinterpret_cast<const float4*>(Sp)[idx];
    }
    const float* fq = g_f + (size_t)(b * NQ + nt * 64) * DIMT + h * DH;
    #pragma unroll
    for (int l = 0; l < 4; l++) {
        int idx = t + l * 256;
        int r = idx >> 4, c = (idx & 15) << 2;
        float4 x = *reinterpret_cast<const float4*>(&fq[(size_t)r * DIMT + c]);
        sqT[c + 0][r] = x.x; sqT[c + 1][r] = x.y;
        sqT[c + 2][r] = x.z; sqT[c + 3][r] = x.w;
        float s = x.x*x.x + x.y*x.y + x.z*x.z + x.w*x.w;
        #pragma unroll
        for (int o = 8; o > 0; o >>= 1) s += __shfl_xor_sync(0xffffffffu, s, o);
        if ((t & 15) == 0) rqn[r] = rsqrtf(s);
    }
    __syncthreads();

    float acc[4][4];
    #pragma unroll
    for (int i = 0; i < 4; i++)
        #pragma unroll
        for (int j = 0; j < 4; j++) acc[i][j] = 0.f;
    const int r0 = (t >> 4) << 2, c0 = (t & 15) << 2;
    #pragma unroll 8
    for (int j1 = 0; j1 < 64; j1++) {
        float4 a  = *reinterpret_cast<float4*>(&sqT[j1][r0]);
        float4 bq = *reinterpret_cast<float4*>(&sS[j1][c0]);
        acc[0][0] = fmaf(a.x, bq.x, acc[0][0]); acc[0][1] = fmaf(a.x, bq.y, acc[0][1]);
        acc[0][2] = fmaf(a.x, bq.z, acc[0][2]); acc[0][3] = fmaf(a.x, bq.w, acc[0][3]);
        acc[1][0] = fmaf(a.y, bq.x, acc[1][0]); acc[1][1] = fmaf(a.y, bq.y, acc[1][1]);
        acc[1][2] = fmaf(a.y, bq.z, acc[1][2]); acc[1][3] = fmaf(a.y, bq.w, acc[1][3]);
        acc[2][0] = fmaf(a.z, bq.x, acc[2][0]); acc[2][1] = fmaf(a.z, bq.y, acc[2][1]);
        acc[2][2] = fmaf(a.z, bq.z, acc[2][2]); acc[2][3] = fmaf(a.z, bq.w, acc[2][3]);
        acc[3][0] = fmaf(a.w, bq.x, acc[3][0]); acc[3][1] = fmaf(a.w, bq.y, acc[3][1]);
        acc[3][2] = fmaf(a.w, bq.z, acc[3][2]); acc[3][3] = fmaf(a.w, bq.w, acc[3][3]);
    }
    const size_t obase = (size_t)(b * NQ + nt * 64 + r0) * DIMT + h * DH + c0;
    #pragma unroll
    for (int i = 0; i < 4; i++) {
        float rq = rqn[r0 + i];
        __nv_bfloat16 h0, h1, h2, h3, l0, l1, l2, l3;
        split2(acc[i][0] * rq, h0, l0); split2(acc[i][1] * rq, h1, l1);
        split2(acc[i][2] * rq, h2, l2); split2(acc[i][3] * rq, h3, l3);
        ushort4 uh = make_ushort4(__bfloat16_as_ushort(h0), __bfloat16_as_ushort(h1),
                                  __bfloat16_as_ushort(h2), __bfloat16_as_ushort(h3));
        ushort4 ul = make_ushort4(__bfloat16_as_ushort(l0), __bfloat16_as_ushort(l1),
                                  __bfloat16_as_ushort(l2), __bfloat16_as_ushort(l3));
        *reinterpret_cast<ushort4*>(g_oh + obase + (size_t)i * DIMT) = uh;
        *reinterpret_cast<ushort4*>(g_ol + obase + (size_t)i * DIMT) = ul;
    }
}

// ---------------------------------------------------------------------------
extern "C" void kernel_launch(void* const* d_in, const int* in_sizes, int n_in,
                              void* d_out, int out_size)
{
    const float* q     = (const float*)d_in[0];
    const float* k     = (const float*)d_in[1];
    const float* v     = (const float*)d_in[2];
    const float* gamma = (const float*)d_in[3];
    const float* beta  = (const float*)d_in[4];
    const float* W_in  = (const float*)d_in[5];
    const float* W_out = (const float*)d_in[6];
    const float* b_out = (const float*)d_in[7];
    float* out = (float*)d_out;

    __nv_bfloat16 *p_ah, *p_al, *p_oh, *p_ol, *p_wih, *p_wil, *p_woh, *p_wol;
    float *p_f;
    cudaGetSymbolAddress((void**)&p_ah,  g_ah);
    cudaGetSymbolAddress((void**)&p_al,  g_al);
    cudaGetSymbolAddress((void**)&p_oh,  g_oh);
    cudaGetSymbolAddress((void**)&p_ol,  g_ol);
    cudaGetSymbolAddress((void**)&p_wih, g_wih);
    cudaGetSymbolAddress((void**)&p_wil, g_wil);
    cudaGetSymbolAddress((void**)&p_woh, g_woh);
    cudaGetSymbolAddress((void**)&p_wol, g_wol);
    cudaGetSymbolAddress((void**)&p_f,   g_f);

    cudaFuncSetAttribute(gemm_mma_bf16x3,
                         cudaFuncAttributeMaxDynamicSharedMemorySize, GSMEM);

    // 0) weight transpose + bf16 split
    wsplit_kernel<<<dim3(32, 32), dim3(32, 8)>>>(W_in,  p_wih, p_wil, DIMT, DIMT);
    wsplit_kernel<<<dim3(32, 32), dim3(32, 8)>>>(W_out, p_woh, p_wol, DIMT, DIMT);
    // 1) LayerNorm q|k|v -> bf16 hi/lo
    ln_kernel<<<ROWS_TOT, 256>>>(q, k, v, gamma, beta);
    // 2) projection GEMM (tensor cores): f = LN(x) @ W_in
    gemm_mma_bf16x3<<<dim3(DIMT / 128, ROWS_TOT / 128), 256, GSMEM>>>(
        p_ah, p_al, p_wih, p_wil, p_f, ROWS_TOT, DIMT, DIMT, nullptr);
    // 3) per-(b,h) S partials + reduce
    kv_part_kernel<<<dim3(BB * NH, KVPARTS), 256>>>();
    s_reduce_kernel<<<BB * NH, 256>>>();
    // 4) attn = q_hat @ S -> bf16 hi/lo
    qs_kernel<<<dim3(NQ / 64, BB * NH), 256>>>();
    // 5) output GEMM (tensor cores): out = attn @ W_out + b_out
    gemm_mma_bf16x3<<<dim3(DIMT / 128, ROWS_Q / 128), 256, GSMEM>>>(
        p_oh, p_ol, p_woh, p_wol, out, ROWS_Q, DIMT, DIMT, b_out);
}

// round 8
// speedup vs baseline: 3.4902x; 1.0048x over previous
#include <cuda_runtime.h>
#include <cuda_bf16.h>
#include <cstdint>

// Problem constants
#define BB     4
#define NQ     1024
#define NK     2048
#define DIMT   1024
#define NH     16
#define DH     64
#define ROWS_Q (BB*NQ)                  // 4096
#define ROWS_K (BB*NK)                  // 8192
#define ROWS_TOT (ROWS_Q + 2*ROWS_K)    // 20480
#define KVPARTS 8

// Scratch (static device arrays: allocation-free per harness rules)
__device__ __nv_bfloat16 g_ah[(size_t)ROWS_TOT * DIMT];  // LN out, hi bf16
__device__ __nv_bfloat16 g_al[(size_t)ROWS_TOT * DIMT];  // LN out, lo bf16
__device__ float         g_f [(size_t)ROWS_TOT * DIMT];  // projected features (fp32)
__device__ float         g_S [BB*NH*DH*DH];              // per-(b,h) 64x64 k_hat^T @ f_v
__device__ float         g_Sp[KVPARTS*BB*NH*DH*DH];      // kv partial sums
__device__ __nv_bfloat16 g_oh[(size_t)ROWS_Q * DIMT];    // attn out, hi bf16
__device__ __nv_bfloat16 g_ol[(size_t)ROWS_Q * DIMT];    // attn out, lo bf16
__device__ __nv_bfloat16 g_wih[DIMT*DIMT], g_wil[DIMT*DIMT];  // W_in^T  hi/lo [N,K]
__device__ __nv_bfloat16 g_woh[DIMT*DIMT], g_wol[DIMT*DIMT];  // W_out^T hi/lo [N,K]

// ---------------------------------------------------------------------------
// Helpers
// ---------------------------------------------------------------------------
__device__ __forceinline__ uint32_t smem_u32(const void* p) {
    uint32_t a;
    asm("{ .reg .u64 t; cvta.to.shared.u64 t, %1; cvt.u32.u64 %0, t; }" : "=r"(a) : "l"(p));
    return a;
}
__device__ __forceinline__ void cp16(uint32_t saddr, const void* g) {
    asm volatile("cp.async.cg.shared.global [%0], [%1], 16;" :: "r"(saddr), "l"(g));
}
#define CP_COMMIT() asm volatile("cp.async.commit_group;" ::: "memory")
#define CP_WAIT(n)  asm volatile("cp.async.wait_group %0;" :: "n"(n) : "memory")

__device__ __forceinline__ void ldsm_x4(uint32_t* r, uint32_t addr) {
    asm volatile("ldmatrix.sync.aligned.m8n8.x4.shared.b16 {%0,%1,%2,%3}, [%4];"
                 : "=r"(r[0]), "=r"(r[1]), "=r"(r[2]), "=r"(r[3]) : "r"(addr));
}
__device__ __forceinline__ void mma16816(float* c, const uint32_t* a, const uint32_t* b) {
    asm volatile("mma.sync.aligned.m16n8k16.row.col.f32.bf16.bf16.f32 "
                 "{%0,%1,%2,%3}, {%4,%5,%6,%7}, {%8,%9}, {%0,%1,%2,%3};"
                 : "+f"(c[0]), "+f"(c[1]), "+f"(c[2]), "+f"(c[3])
                 : "r"(a[0]), "r"(a[1]), "r"(a[2]), "r"(a[3]), "r"(b[0]), "r"(b[1]));
}
__device__ __forceinline__ void split2(float x, __nv_bfloat16& h, __nv_bfloat16& l) {
    h = __float2bfloat16_rn(x);
    l = __float2bfloat16_rn(x - __bfloat162float(h));
}
// XOR chunk swizzle for 64B rows of 4x16B chunks: 16B-aligned, ldmatrix
// 8-row phases hit all 8 banks.
__device__ __forceinline__ uint32_t sw_off(uint32_t row, uint32_t chunk) {
    return row * 64u + (chunk ^ ((row >> 1) & 3u)) * 16u;
}

// ---------------------------------------------------------------------------
// Kernel 1 (merged): blockIdx < ROWS_TOT  -> LayerNorm row -> bf16 hi/lo.
// next 1024 blocks -> W_in transpose+split tile; next 1024 -> W_out.
// One launch instead of three: weight split rides inside the LN wave.
// ---------------------------------------------------------------------------
__global__ void __launch_bounds__(256) prep_kernel(
    const float* __restrict__ q, const float* __restrict__ k,
    const float* __restrict__ v, const float* __restrict__ gamma,
    const float* __restrict__ beta,
    const float* __restrict__ W_in, const float* __restrict__ W_out)
{
    const int blk = blockIdx.x;
    const int t = threadIdx.x;

    if (blk >= ROWS_TOT) {
        // ---- weight transpose + split tile ----
        __shared__ float ts[32][33];
        int wblk = blk - ROWS_TOT;
        const float* W = (wblk < 1024) ? W_in : W_out;
        __nv_bfloat16* Th = (wblk < 1024) ? g_wih : g_woh;
        __nv_bfloat16* Tl = (wblk < 1024) ? g_wil : g_wol;
        wblk &= 1023;
        int n0 = (wblk & 31) * 32, k0 = (wblk >> 5) * 32;
        int tx = t & 31, ty = t >> 5;                    // 32 x 8
        #pragma unroll
        for (int j = 0; j < 4; j++)
            ts[ty + j * 8][tx] = W[(size_t)(k0 + ty + j * 8) * DIMT + n0 + tx];
        __syncthreads();
        #pragma unroll
        for (int j = 0; j < 4; j++) {
            int n = n0 + ty + j * 8, kk = k0 + tx;
            float x = ts[tx][ty + j * 8];
            __nv_bfloat16 h, l;
            split2(x, h, l);
            Th[(size_t)n * DIMT + kk] = h;
            Tl[(size_t)n * DIMT + kk] = l;
        }
        return;
    }

    // ---- LayerNorm row ----
    int row = blk;
    const float* src;
    if (row < ROWS_Q)               src = q + (size_t)row * DIMT;
    else if (row < ROWS_Q + ROWS_K) src = k + (size_t)(row - ROWS_Q) * DIMT;
    else                            src = v + (size_t)(row - ROWS_Q - ROWS_K) * DIMT;

    float4 x = reinterpret_cast<const float4*>(src)[t];
    float s  = x.x + x.y + x.z + x.w;
    float ss = x.x*x.x + x.y*x.y + x.z*x.z + x.w*x.w;
    #pragma unroll
    for (int o = 16; o > 0; o >>= 1) {
        s  += __shfl_xor_sync(0xffffffffu, s,  o);
        ss += __shfl_xor_sync(0xffffffffu, ss, o);
    }
    __shared__ float ws[8], wss[8];
    int wid = t >> 5, lane = t & 31;
    if (lane == 0) { ws[wid] = s; wss[wid] = ss; }
    __syncthreads();
    float tot = 0.f, totss = 0.f;
    #pragma unroll
    for (int i = 0; i < 8; i++) { tot += ws[i]; totss += wss[i]; }
    float mu  = tot * (1.0f / DIMT);
    float var = totss * (1.0f / DIMT) - mu * mu;       // biased, matches ref
    float rs  = rsqrtf(var + 1e-5f);

    float4 g  = reinterpret_cast<const float4*>(gamma)[t];
    float4 be = reinterpret_cast<const float4*>(beta)[t];
    float y0 = (x.x - mu) * rs * g.x + be.x;
    float y1 = (x.y - mu) * rs * g.y + be.y;
    float y2 = (x.z - mu) * rs * g.z + be.z;
    float y3 = (x.w - mu) * rs * g.w + be.w;

    __nv_bfloat16 h0, h1, h2, h3, l0, l1, l2, l3;
    split2(y0, h0, l0); split2(y1, h1, l1); split2(y2, h2, l2); split2(y3, h3, l3);
    ushort4 uh = make_ushort4(__bfloat16_as_ushort(h0), __bfloat16_as_ushort(h1),
                              __bfloat16_as_ushort(h2), __bfloat16_as_ushort(h3));
    ushort4 ul = make_ushort4(__bfloat16_as_ushort(l0), __bfloat16_as_ushort(l1),
                              __bfloat16_as_ushort(l2), __bfloat16_as_ushort(l3));
    reinterpret_cast<ushort4*>(g_ah + (size_t)row * DIMT)[t] = uh;
    reinterpret_cast<ushort4*>(g_al + (size_t)row * DIMT)[t] = ul;
}

// ---------------------------------------------------------------------------
// Kernel 2: mma.sync bf16x3 GEMM.  C[M,N] = A[M,K] @ Bt[N,K]^T (+bias).
// 128x128 tile, BK=32, 256 threads (8 warps, 2x4), warp tile 64x32.
// 3-stage cp.async pipeline, one __syncthreads per slab; XOR-swizzled 64B rows.
// MMA passes issued nt-major per mt (dependency distance 4 between RAW-linked
// HMMAs on the same accumulator, instead of back-to-back triplets).
// ---------------------------------------------------------------------------
#define BKG     32
#define ROWB    64                     // 64 B per row (32 bf16, unpadded)
#define TILE_B  (128 * ROWB)           // 8192 B per tensor tile
#define STAGE_B (4 * TILE_B)           // 32768 B per stage
#define GSMEM   (3 * STAGE_B)          // 98304 B total

__global__ void __launch_bounds__(256, 2) gemm_mma_bf16x3(
    const __nv_bfloat16* __restrict__ Ah, const __nv_bfloat16* __restrict__ Al,
    const __nv_bfloat16* __restrict__ Bh, const __nv_bfloat16* __restrict__ Bl,
    float* __restrict__ C, int M, int N, int K, const float* __restrict__ bias)
{
    extern __shared__ char sm[];
    const uint32_t sbase = smem_u32(sm);
    const int tid = threadIdx.x;
    const int lane = tid & 31;
    const int wid = tid >> 5;
    const int warp_m = wid >> 2;        // 0..1
    const int warp_n = wid & 3;         // 0..3
    const int brow = blockIdx.y, bcol = blockIdx.x;

    const __nv_bfloat16* tp[4] = {
        Ah + (size_t)brow * 128 * K, Al + (size_t)brow * 128 * K,
        Bh + (size_t)bcol * 128 * K, Bl + (size_t)bcol * 128 * K };

    // per-thread fixed load mapping: 8 chunks of 16B (2048 chunks / 256 thr)
    int l_tens[8], l_row[8], l_ch[8];
    #pragma unroll
    for (int l = 0; l < 8; l++) {
        int id = l * 256 + tid;
        l_tens[l] = id >> 9;
        int u = id & 511;
        l_row[l] = u >> 2;
        l_ch[l] = u & 3;
    }

    float acc[4][4][4];
    #pragma unroll
    for (int i = 0; i < 4; i++)
        #pragma unroll
        for (int j = 0; j < 4; j++)
            #pragma unroll
            for (int c = 0; c < 4; c++) acc[i][j][c] = 0.f;

    const int NS = K / BKG;             // 32 slabs

    // prologue: slabs 0 and 1
    #pragma unroll
    for (int pr = 0; pr < 2; pr++) {
        #pragma unroll
        for (int l = 0; l < 8; l++) {
            uint32_t sa = sbase + pr * STAGE_B + l_tens[l] * TILE_B
                        + sw_off((uint32_t)l_row[l], (uint32_t)l_ch[l]);
            cp16(sa, tp[l_tens[l]] + (size_t)l_row[l] * K + pr * BKG + l_ch[l] * 8);
        }
        CP_COMMIT();
    }

    // ldmatrix lane mappings (logical chunk = kk*2 + lane k-bit, swizzled per row)
    const int b_rowlane = ((lane >> 4) & 1) * 8 + (lane & 7);
    const uint32_t b_kbit = (uint32_t)((lane >> 3) & 1);
    const uint32_t a_kbit = (uint32_t)(lane >> 4);
    const int bn = warp_n * 32;

    for (int ks = 0; ks < NS; ks++) {
        if (ks + 2 < NS) CP_WAIT(1); else CP_WAIT(0);
        __syncthreads();

        // prefetch slab ks+2 into stage (ks+2)%3
        if (ks + 2 < NS) {
            const int st = (ks + 2) % 3;
            const int k0 = (ks + 2) * BKG;
            #pragma unroll
            for (int l = 0; l < 8; l++) {
                uint32_t sa = sbase + st * STAGE_B + l_tens[l] * TILE_B
                            + sw_off((uint32_t)l_row[l], (uint32_t)l_ch[l]);
                cp16(sa, tp[l_tens[l]] + (size_t)l_row[l] * K + k0 + l_ch[l] * 8);
            }
            CP_COMMIT();
        }

        const uint32_t stb = sbase + (ks % 3) * STAGE_B;
        #pragma unroll
        for (int kk = 0; kk < 2; kk++) {          // two k16 halves of BK=32
            const uint32_t bchunk = (uint32_t)(kk * 2) + b_kbit;
            const uint32_t achunk = (uint32_t)(kk * 2) + a_kbit;
            // B fragments: 2 ldsm_x4 per tensor cover 4 n-tiles x 2 k-halves
            uint32_t bh[4][2], bl[4][2];
            #pragma unroll
            for (int p = 0; p < 2; p++) {
                uint32_t brr = (uint32_t)(bn + p * 16 + b_rowlane);
                uint32_t boff = sw_off(brr, bchunk);
                uint32_t r4[4];
                ldsm_x4(r4, stb + 2 * TILE_B + boff);
                bh[2*p][0] = r4[0]; bh[2*p][1] = r4[1];
                bh[2*p+1][0] = r4[2]; bh[2*p+1][1] = r4[3];
                ldsm_x4(r4, stb + 3 * TILE_B + boff);
                bl[2*p][0] = r4[0]; bl[2*p][1] = r4[1];
                bl[2*p+1][0] = r4[2]; bl[2*p+1][1] = r4[3];
            }
            #pragma unroll
            for (int mt = 0; mt < 4; mt++) {
                uint32_t ah4[4], al4[4];
                uint32_t arr = (uint32_t)(warp_m * 64 + mt * 16 + (lane & 15));
                uint32_t aoff = sw_off(arr, achunk);
                ldsm_x4(ah4, stb + aoff);
                ldsm_x4(al4, stb + TILE_B + aoff);
                // pass-major: RAW-dependent MMAs on acc[mt][nt] are 4 apart
                #pragma unroll
                for (int nt = 0; nt < 4; nt++) mma16816(acc[mt][nt], ah4, bh[nt]);
                #pragma unroll
                for (int nt = 0; nt < 4; nt++) mma16816(acc[mt][nt], ah4, bl[nt]);
                #pragma unroll
                for (int nt = 0; nt < 4; nt++) mma16816(acc[mt][nt], al4, bh[nt]);
            }
        }
    }

    // epilogue
    #pragma unroll
    for (int mt = 0; mt < 4; mt++) {
        const int row0 = brow * 128 + warp_m * 64 + mt * 16 + (lane >> 2);
        #pragma unroll
        for (int nt = 0; nt < 4; nt++) {
            const int col = bcol * 128 + warp_n * 32 + nt * 8 + (lane & 3) * 2;
            float b0 = 0.f, b1 = 0.f;
            if (bias) { b0 = __ldg(&bias[col]); b1 = __ldg(&bias[col + 1]); }
            *reinterpret_cast<float2*>(C + (size_t)row0 * N + col) =
                make_float2(acc[mt][nt][0] + b0, acc[mt][nt][1] + b1);
            *reinterpret_cast<float2*>(C + (size_t)(row0 + 8) * N + col) =
                make_float2(acc[mt][nt][2] + b0, acc[mt][nt][3] + b1);
        }
    }
}

// ---------------------------------------------------------------------------
// Kernel 3: kv partials. grid = (64, KVPARTS) -> 512 CTAs (full-chip).
// ---------------------------------------------------------------------------
__global__ void __launch_bounds__(256) kv_part_kernel()
{
    const int bh = blockIdx.x;
    const int part = blockIdx.y;
    const int b = bh >> 4, h = bh & 15;
    __shared__ float sk[32][64];
    __shared__ float sv[32][64];
    __shared__ float rkn[32];
    const int t = threadIdx.x;
    const int j1_0 = (t >> 4) << 2;
    const int j2_0 = (t & 15) << 2;
    const int mbase = part * (NK / KVPARTS);
    const float* fk = g_f + (size_t)(ROWS_Q + b * NK + mbase) * DIMT + h * DH;
    const float* fv = g_f + (size_t)(ROWS_Q + ROWS_K + b * NK + mbase) * DIMT + h * DH;

    float acc[4][4];
    #pragma unroll
    for (int i = 0; i < 4; i++)
        #pragma unroll
        for (int j = 0; j < 4; j++) acc[i][j] = 0.f;

    for (int m0 = 0; m0 < NK / KVPARTS; m0 += 32) {
        #pragma unroll
        for (int l = 0; l < 2; l++) {
            int idx = t + l * 256;
            int r = idx >> 4, c = (idx & 15) << 2;
            float4 kv4 = *reinterpret_cast<const float4*>(&fk[(size_t)(m0 + r) * DIMT + c]);
            float4 vv4 = *reinterpret_cast<const float4*>(&fv[(size_t)(m0 + r) * DIMT + c]);
            *reinterpret_cast<float4*>(&sk[r][c]) = kv4;
            *reinterpret_cast<float4*>(&sv[r][c]) = vv4;
            float s = kv4.x*kv4.x + kv4.y*kv4.y + kv4.z*kv4.z + kv4.w*kv4.w;
            #pragma unroll
            for (int o = 8; o > 0; o >>= 1) s += __shfl_xor_sync(0xffffffffu, s, o);
            if ((t & 15) == 0) rkn[r] = rsqrtf(s);
        }
        __syncthreads();
        #pragma unroll 8
        for (int m = 0; m < 32; m++) {
            float rk = rkn[m];
            float4 a  = *reinterpret_cast<float4*>(&sk[m][j1_0]);
            float4 bq = *reinterpret_cast<float4*>(&sv[m][j2_0]);
            float a0 = a.x * rk, a1 = a.y * rk, a2 = a.z * rk, a3 = a.w * rk;
            acc[0][0] = fmaf(a0, bq.x, acc[0][0]); acc[0][1] = fmaf(a0, bq.y, acc[0][1]);
            acc[0][2] = fmaf(a0, bq.z, acc[0][2]); acc[0][3] = fmaf(a0, bq.w, acc[0][3]);
            acc[1][0] = fmaf(a1, bq.x, acc[1][0]); acc[1][1] = fmaf(a1, bq.y, acc[1][1]);
            acc[1][2] = fmaf(a1, bq.z, acc[1][2]); acc[1][3] = fmaf(a1, bq.w, acc[1][3]);
            acc[2][0] = fmaf(a2, bq.x, acc[2][0]); acc[2][1] = fmaf(a2, bq.y, acc[2][1]);
            acc[2][2] = fmaf(a2, bq.z, acc[2][2]); acc[2][3] = fmaf(a2, bq.w, acc[2][3]);
            acc[3][0] = fmaf(a3, bq.x, acc[3][0]); acc[3][1] = fmaf(a3, bq.y, acc[3][1]);
            acc[3][2] = fmaf(a3, bq.z, acc[3][2]); acc[3][3] = fmaf(a3, bq.w, acc[3][3]);
        }
        __syncthreads();
    }
    float* Sp = g_Sp + ((size_t)part * (BB * NH) + bh) * (DH * DH);
    #pragma unroll
    for (int i = 0; i < 4; i++)
        *reinterpret_cast<float4*>(&Sp[(j1_0 + i) * DH + j2_0]) =
            make_float4(acc[i][0], acc[i][1], acc[i][2], acc[i][3]);
}

// Reduce KVPARTS partials into g_S. grid=64, block=256; 4 float4 per thread.
__global__ void __launch_bounds__(256) s_reduce_kernel()
{
    const int bh = blockIdx.x;
    const int t = threadIdx.x;
    const size_t base = (size_t)bh * (DH * DH);
    #pragma unroll
    for (int l = 0; l < 4; l++) {
        int idx = t + l * 256;                       // 1024 float4s per matrix
        float4 s = make_float4(0.f, 0.f, 0.f, 0.f);
        #pragma unroll
        for (int p = 0; p < KVPARTS; p++) {
            float4 v = reinterpret_cast<const float4*>(
                g_Sp + ((size_t)p * (BB * NH)) * (DH * DH) + base)[idx];
            s.x += v.x; s.y += v.y; s.z += v.z; s.w += v.w;
        }
        reinterpret_cast<float4*>(g_S + base)[idx] = s;
    }
}

// ---------------------------------------------------------------------------
// Kernel 4: out_attn = (f_q/|f_q|) @ S[b,h]  -> bf16 hi/lo split, heads merged.
// ---------------------------------------------------------------------------
__global__ void __launch_bounds__(256) qs_kernel()
{
    const int bh = blockIdx.y;
    const int nt = blockIdx.x;
    const int b = bh >> 4, h = bh & 15;
    __shared__ float sS[64][64];
    __shared__ float sqT[64][64];
    __shared__ float rqn[64];
    const int t = threadIdx.x;

    const float* Sp = g_S + (size_t)bh * (DH * DH);
    #pragma unroll
    for (int l = 0; l < 4; l++) {
        int idx = t + l * 256;
        reinterpret_cast<float4*>(sS)[idx] = reinterpret_cast<const float4*>(Sp)[idx];
    }
    const float* fq = g_f + (size_t)(b * NQ + nt * 64) * DIMT + h * DH;
    #pragma unroll
    for (int l = 0; l < 4; l++) {
        int idx = t + l * 256;
        int r = idx >> 4, c = (idx & 15) << 2;
        float4 x = *reinterpret_cast<const float4*>(&fq[(size_t)r * DIMT + c]);
        sqT[c + 0][r] = x.x; sqT[c + 1][r] = x.y;
        sqT[c + 2][r] = x.z; sqT[c + 3][r] = x.w;
        float s = x.x*x.x + x.y*x.y + x.z*x.z + x.w*x.w;
        #pragma unroll
        for (int o = 8; o > 0; o >>= 1) s += __shfl_xor_sync(0xffffffffu, s, o);
        if ((t & 15) == 0) rqn[r] = rsqrtf(s);
    }
    __syncthreads();

    float acc[4][4];
    #pragma unroll
    for (int i = 0; i < 4; i++)
        #pragma unroll
        for (int j = 0; j < 4; j++) acc[i][j] = 0.f;
    const int r0 = (t >> 4) << 2, c0 = (t & 15) << 2;
    #pragma unroll 8
    for (int j1 = 0; j1 < 64; j1++) {
        float4 a  = *reinterpret_cast<float4*>(&sqT[j1][r0]);
        float4 bq = *reinterpret_cast<float4*>(&sS[j1][c0]);
        acc[0][0] = fmaf(a.x, bq.x, acc[0][0]); acc[0][1] = fmaf(a.x, bq.y, acc[0][1]);
        acc[0][2] = fmaf(a.x, bq.z, acc[0][2]); acc[0][3] = fmaf(a.x, bq.w, acc[0][3]);
        acc[1][0] = fmaf(a.y, bq.x, acc[1][0]); acc[1][1] = fmaf(a.y, bq.y, acc[1][1]);
        acc[1][2] = fmaf(a.y, bq.z, acc[1][2]); acc[1][3] = fmaf(a.y, bq.w, acc[1][3]);
        acc[2][0] = fmaf(a.z, bq.x, acc[2][0]); acc[2][1] = fmaf(a.z, bq.y, acc[2][1]);
        acc[2][2] = fmaf(a.z, bq.z, acc[2][2]); acc[2][3] = fmaf(a.z, bq.w, acc[2][3]);
        acc[3][0] = fmaf(a.w, bq.x, acc[3][0]); acc[3][1] = fmaf(a.w, bq.y, acc[3][1]);
        acc[3][2] = fmaf(a.w, bq.z, acc[3][2]); acc[3][3] = fmaf(a.w, bq.w, acc[3][3]);
    }
    const size_t obase = (size_t)(b * NQ + nt * 64 + r0) * DIMT + h * DH + c0;
    #pragma unroll
    for (int i = 0; i < 4; i++) {
        float rq = rqn[r0 + i];
        __nv_bfloat16 h0, h1, h2, h3, l0, l1, l2, l3;
        split2(acc[i][0] * rq, h0, l0); split2(acc[i][1] * rq, h1, l1);
        split2(acc[i][2] * rq, h2, l2); split2(acc[i][3] * rq, h3, l3);
        ushort4 uh = make_ushort4(__bfloat16_as_ushort(h0), __bfloat16_as_ushort(h1),
                                  __bfloat16_as_ushort(h2), __bfloat16_as_ushort(h3));
        ushort4 ul = make_ushort4(__bfloat16_as_ushort(l0), __bfloat16_as_ushort(l1),
                                  __bfloat16_as_ushort(l2), __bfloat16_as_ushort(l3));
        *reinterpret_cast<ushort4*>(g_oh + obase + (size_t)i * DIMT) = uh;
        *reinterpret_cast<ushort4*>(g_ol + obase + (size_t)i * DIMT) = ul;
    }
}

// ---------------------------------------------------------------------------
extern "C" void kernel_launch(void* const* d_in, const int* in_sizes, int n_in,
                              void* d_out, int out_size)
{
    const float* q     = (const float*)d_in[0];
    const float* k     = (const float*)d_in[1];
    const float* v     = (const float*)d_in[2];
    const float* gamma = (const float*)d_in[3];
    const float* beta  = (const float*)d_in[4];
    const float* W_in  = (const float*)d_in[5];
    const float* W_out = (const float*)d_in[6];
    const float* b_out = (const float*)d_in[7];
    float* out = (float*)d_out;

    __nv_bfloat16 *p_ah, *p_al, *p_oh, *p_ol, *p_wih, *p_wil, *p_woh, *p_wol;
    float *p_f;
    cudaGetSymbolAddress((void**)&p_ah,  g_ah);
    cudaGetSymbolAddress((void**)&p_al,  g_al);
    cudaGetSymbolAddress((void**)&p_oh,  g_oh);
    cudaGetSymbolAddress((void**)&p_ol,  g_ol);
    cudaGetSymbolAddress((void**)&p_wih, g_wih);
    cudaGetSymbolAddress((void**)&p_wil, g_wil);
    cudaGetSymbolAddress((void**)&p_woh, g_woh);
    cudaGetSymbolAddress((void**)&p_wol, g_wol);
    cudaGetSymbolAddress((void**)&p_f,   g_f);

    cudaFuncSetAttribute(gemm_mma_bf16x3,
                         cudaFuncAttributeMaxDynamicSharedMemorySize, GSMEM);

    // 1) LayerNorm q|k|v -> bf16 hi/lo  +  weight transpose/split (one launch)
    prep_kernel<<<ROWS_TOT + 2048, 256>>>(q, k, v, gamma, beta, W_in, W_out);
    // 2) projection GEMM (tensor cores): f = LN(x) @ W_in
    gemm_mma_bf16x3<<<dim3(DIMT / 128, ROWS_TOT / 128), 256, GSMEM>>>(
        p_ah, p_al, p_wih, p_wil, p_f, ROWS_TOT, DIMT, DIMT, nullptr);
    // 3) per-(b,h) S partials + reduce
    kv_part_kernel<<<dim3(BB * NH, KVPARTS), 256>>>();
    s_reduce_kernel<<<BB * NH, 256>>>();
    // 4) attn = q_hat @ S -> bf16 hi/lo
    qs_kernel<<<dim3(NQ / 64, BB * NH), 256>>>();
    // 5) output GEMM (tensor cores): out = attn @ W_out + b_out
    gemm_mma_bf16x3<<<dim3(DIMT / 128, ROWS_Q / 128), 256, GSMEM>>>(
        p_oh, p_ol, p_woh, p_wol, out, ROWS_Q, DIMT, DIMT, b_out);
}

// round 9
// speedup vs baseline: 3.6650x; 1.0501x over previous
#include <cuda_runtime.h>
#include <cuda_bf16.h>
#include <cstdint>

// Problem constants
#define BB     4
#define NQ     1024
#define NK     2048
#define DIMT   1024
#define NH     16
#define DH     64
#define ROWS_Q (BB*NQ)                  // 4096
#define ROWS_K (BB*NK)                  // 8192
#define ROWS_TOT (ROWS_Q + 2*ROWS_K)    // 20480
#define KVPARTS 8

// GEMM1 tail-split constants: 1280 tiles total, 1184 full-K + 96 split-K(2)
#define G1_TILES     1280
#define G1_FULL      1184
#define G1_SPLIT     (G1_TILES - G1_FULL)          // 96
#define G1_GRID      (G1_FULL + 2 * G1_SPLIT)      // 1376
#define SPLIT_ROW0   (148 * 128)                   // first row of split tiles

// Scratch (static device arrays: allocation-free per harness rules)
__device__ __nv_bfloat16 g_ah[(size_t)ROWS_TOT * DIMT];  // LN out, hi bf16
__device__ __nv_bfloat16 g_al[(size_t)ROWS_TOT * DIMT];  // LN out, lo bf16
__device__ float         g_f [(size_t)ROWS_TOT * DIMT];  // projected features (fp32)
__device__ float         g_S [BB*NH*DH*DH];              // per-(b,h) 64x64 k_hat^T @ f_v
__device__ float         g_Sp[KVPARTS*BB*NH*DH*DH];      // kv partial sums
__device__ __nv_bfloat16 g_oh[(size_t)ROWS_Q * DIMT];    // attn out, hi bf16
__device__ __nv_bfloat16 g_ol[(size_t)ROWS_Q * DIMT];    // attn out, lo bf16
__device__ __nv_bfloat16 g_wih[DIMT*DIMT], g_wil[DIMT*DIMT];  // W_in^T  hi/lo [N,K]
__device__ __nv_bfloat16 g_woh[DIMT*DIMT], g_wol[DIMT*DIMT];  // W_out^T hi/lo [N,K]

// ---------------------------------------------------------------------------
// Helpers
// ---------------------------------------------------------------------------
__device__ __forceinline__ uint32_t smem_u32(const void* p) {
    uint32_t a;
    asm("{ .reg .u64 t; cvta.to.shared.u64 t, %1; cvt.u32.u64 %0, t; }" : "=r"(a) : "l"(p));
    return a;
}
__device__ __forceinline__ void cp16(uint32_t saddr, const void* g) {
    asm volatile("cp.async.cg.shared.global [%0], [%1], 16;" :: "r"(saddr), "l"(g));
}
#define CP_COMMIT() asm volatile("cp.async.commit_group;" ::: "memory")
#define CP_WAIT(n)  asm volatile("cp.async.wait_group %0;" :: "n"(n) : "memory")

__device__ __forceinline__ void ldsm_x4(uint32_t* r, uint32_t addr) {
    asm volatile("ldmatrix.sync.aligned.m8n8.x4.shared.b16 {%0,%1,%2,%3}, [%4];"
                 : "=r"(r[0]), "=r"(r[1]), "=r"(r[2]), "=r"(r[3]) : "r"(addr));
}
__device__ __forceinline__ void mma16816(float* c, const uint32_t* a, const uint32_t* b) {
    asm volatile("mma.sync.aligned.m16n8k16.row.col.f32.bf16.bf16.f32 "
                 "{%0,%1,%2,%3}, {%4,%5,%6,%7}, {%8,%9}, {%0,%1,%2,%3};"
                 : "+f"(c[0]), "+f"(c[1]), "+f"(c[2]), "+f"(c[3])
                 : "r"(a[0]), "r"(a[1]), "r"(a[2]), "r"(a[3]), "r"(b[0]), "r"(b[1]));
}
__device__ __forceinline__ void split2(float x, __nv_bfloat16& h, __nv_bfloat16& l) {
    h = __float2bfloat16_rn(x);
    l = __float2bfloat16_rn(x - __bfloat162float(h));
}
// XOR chunk swizzle for 64B rows of 4x16B chunks: 16B-aligned, ldmatrix
// 8-row phases hit all 8 banks.
__device__ __forceinline__ uint32_t sw_off(uint32_t row, uint32_t chunk) {
    return row * 64u + (chunk ^ ((row >> 1) & 3u)) * 16u;
}

// ---------------------------------------------------------------------------
// Kernel 1 (merged): LN rows | weight transpose/split | zero split-tile region
// blk < ROWS_TOT                 : LayerNorm row -> bf16 hi/lo
// next 2048                      : W_in / W_out transpose+split tile
// next 1536                      : zero one g_f row in [SPLIT_ROW0, 20480)
// ---------------------------------------------------------------------------
__global__ void __launch_bounds__(256) prep_kernel(
    const float* __restrict__ q, const float* __restrict__ k,
    const float* __restrict__ v, const float* __restrict__ gamma,
    const float* __restrict__ beta,
    const float* __restrict__ W_in, const float* __restrict__ W_out)
{
    const int blk = blockIdx.x;
    const int t = threadIdx.x;

    if (blk >= ROWS_TOT + 2048) {
        // ---- zero one g_f row of the split-K accumulation region ----
        int zrow = SPLIT_ROW0 + (blk - ROWS_TOT - 2048);
        reinterpret_cast<float4*>(g_f + (size_t)zrow * DIMT)[t] =
            make_float4(0.f, 0.f, 0.f, 0.f);
        return;
    }
    if (blk >= ROWS_TOT) {
        // ---- weight transpose + split tile ----
        __shared__ float ts[32][33];
        int wblk = blk - ROWS_TOT;
        const float* W = (wblk < 1024) ? W_in : W_out;
        __nv_bfloat16* Th = (wblk < 1024) ? g_wih : g_woh;
        __nv_bfloat16* Tl = (wblk < 1024) ? g_wil : g_wol;
        wblk &= 1023;
        int n0 = (wblk & 31) * 32, k0 = (wblk >> 5) * 32;
        int tx = t & 31, ty = t >> 5;                    // 32 x 8
        #pragma unroll
        for (int j = 0; j < 4; j++)
            ts[ty + j * 8][tx] = W[(size_t)(k0 + ty + j * 8) * DIMT + n0 + tx];
        __syncthreads();
        #pragma unroll
        for (int j = 0; j < 4; j++) {
            int n = n0 + ty + j * 8, kk = k0 + tx;
            float x = ts[tx][ty + j * 8];
            __nv_bfloat16 h, l;
            split2(x, h, l);
            Th[(size_t)n * DIMT + kk] = h;
            Tl[(size_t)n * DIMT + kk] = l;
        }
        return;
    }

    // ---- LayerNorm row ----
    int row = blk;
    const float* src;
    if (row < ROWS_Q)               src = q + (size_t)row * DIMT;
    else if (row < ROWS_Q + ROWS_K) src = k + (size_t)(row - ROWS_Q) * DIMT;
    else                            src = v + (size_t)(row - ROWS_Q - ROWS_K) * DIMT;

    float4 x = reinterpret_cast<const float4*>(src)[t];
    float s  = x.x + x.y + x.z + x.w;
    float ss = x.x*x.x + x.y*x.y + x.z*x.z + x.w*x.w;
    #pragma unroll
    for (int o = 16; o > 0; o >>= 1) {
        s  += __shfl_xor_sync(0xffffffffu, s,  o);
        ss += __shfl_xor_sync(0xffffffffu, ss, o);
    }
    __shared__ float ws[8], wss[8];
    int wid = t >> 5, lane = t & 31;
    if (lane == 0) { ws[wid] = s; wss[wid] = ss; }
    __syncthreads();
    float tot = 0.f, totss = 0.f;
    #pragma unroll
    for (int i = 0; i < 8; i++) { tot += ws[i]; totss += wss[i]; }
    float mu  = tot * (1.0f / DIMT);
    float var = totss * (1.0f / DIMT) - mu * mu;       // biased, matches ref
    float rs  = rsqrtf(var + 1e-5f);

    float4 g  = reinterpret_cast<const float4*>(gamma)[t];
    float4 be = reinterpret_cast<const float4*>(beta)[t];
    float y0 = (x.x - mu) * rs * g.x + be.x;
    float y1 = (x.y - mu) * rs * g.y + be.y;
    float y2 = (x.z - mu) * rs * g.z + be.z;
    float y3 = (x.w - mu) * rs * g.w + be.w;

    __nv_bfloat16 h0, h1, h2, h3, l0, l1, l2, l3;
    split2(y0, h0, l0); split2(y1, h1, l1); split2(y2, h2, l2); split2(y3, h3, l3);
    ushort4 uh = make_ushort4(__bfloat16_as_ushort(h0), __bfloat16_as_ushort(h1),
                              __bfloat16_as_ushort(h2), __bfloat16_as_ushort(h3));
    ushort4 ul = make_ushort4(__bfloat16_as_ushort(l0), __bfloat16_as_ushort(l1),
                              __bfloat16_as_ushort(l2), __bfloat16_as_ushort(l3));
    reinterpret_cast<ushort4*>(g_ah + (size_t)row * DIMT)[t] = uh;
    reinterpret_cast<ushort4*>(g_al + (size_t)row * DIMT)[t] = ul;
}

// ---------------------------------------------------------------------------
// Kernel 2: mma.sync bf16x3 GEMM, flat grid with split-K tail wave.
// bid < n_full: tile=bid, full K.   bid >= n_full: two CTAs per remaining
// tile, each half of K, accumulating into zero-initialized C via atomicAdd
// (2 contributions onto 0 -> bitwise order-invariant, deterministic).
// 128x128 tile, BK=32, 3-stage cp.async, XOR-swizzled 64B rows.
// ---------------------------------------------------------------------------
#define BKG     32
#define ROWB    64                     // 64 B per row (32 bf16, unpadded)
#define TILE_B  (128 * ROWB)           // 8192 B per tensor tile
#define STAGE_B (4 * TILE_B)           // 32768 B per stage
#define GSMEM   (3 * STAGE_B)          // 98304 B total

__global__ void __launch_bounds__(256, 2) gemm_mma_bf16x3(
    const __nv_bfloat16* __restrict__ Ah, const __nv_bfloat16* __restrict__ Al,
    const __nv_bfloat16* __restrict__ Bh, const __nv_bfloat16* __restrict__ Bl,
    float* __restrict__ C, int M, int N, int K, const float* __restrict__ bias,
    int n_full)
{
    extern __shared__ char sm[];
    const uint32_t sbase = smem_u32(sm);
    const int tid = threadIdx.x;
    const int lane = tid & 31;
    const int wid = tid >> 5;
    const int warp_m = wid >> 2;        // 0..1
    const int warp_n = wid & 3;         // 0..3

    // tile / K-range resolution (N/128 == 8 for all uses)
    const int bid = blockIdx.x;
    int tile, k_begin, k_slabs;
    bool is_split;
    if (bid < n_full) {
        tile = bid; k_begin = 0; k_slabs = K / BKG; is_split = false;
    } else {
        int j = bid - n_full;
        tile = n_full + (j >> 1);
        k_begin = (j & 1) * (K / 2);
        k_slabs = K / (2 * BKG);
        is_split = true;
    }
    const int brow = tile >> 3, bcol = tile & 7;

    const __nv_bfloat16* tp[4] = {
        Ah + (size_t)brow * 128 * K + k_begin,
        Al + (size_t)brow * 128 * K + k_begin,
        Bh + (size_t)bcol * 128 * K + k_begin,
        Bl + (size_t)bcol * 128 * K + k_begin };

    // per-thread fixed load mapping: 8 chunks of 16B (2048 chunks / 256 thr)
    int l_tens[8], l_row[8], l_ch[8];
    #pragma unroll
    for (int l = 0; l < 8; l++) {
        int id = l * 256 + tid;
        l_tens[l] = id >> 9;
        int u = id & 511;
        l_row[l] = u >> 2;
        l_ch[l] = u & 3;
    }

    float acc[4][4][4];
    #pragma unroll
    for (int i = 0; i < 4; i++)
        #pragma unroll
        for (int j = 0; j < 4; j++)
            #pragma unroll
            for (int c = 0; c < 4; c++) acc[i][j][c] = 0.f;

    // prologue: slabs 0 and 1
    #pragma unroll
    for (int pr = 0; pr < 2; pr++) {
        #pragma unroll
        for (int l = 0; l < 8; l++) {
            uint32_t sa = sbase + pr * STAGE_B + l_tens[l] * TILE_B
                        + sw_off((uint32_t)l_row[l], (uint32_t)l_ch[l]);
            cp16(sa, tp[l_tens[l]] + (size_t)l_row[l] * K + pr * BKG + l_ch[l] * 8);
        }
        CP_COMMIT();
    }

    // ldmatrix lane mappings
    const int b_rowlane = ((lane >> 4) & 1) * 8 + (lane & 7);
    const uint32_t b_kbit = (uint32_t)((lane >> 3) & 1);
    const uint32_t a_kbit = (uint32_t)(lane >> 4);
    const int bn = warp_n * 32;

    for (int ks = 0; ks < k_slabs; ks++) {
        if (ks + 2 < k_slabs) CP_WAIT(1); else CP_WAIT(0);
        __syncthreads();

        // prefetch slab ks+2 into stage (ks+2)%3
        if (ks + 2 < k_slabs) {
            const int st = (ks + 2) % 3;
            const int k0 = (ks + 2) * BKG;
            #pragma unroll
            for (int l = 0; l < 8; l++) {
                uint32_t sa = sbase + st * STAGE_B + l_tens[l] * TILE_B
                            + sw_off((uint32_t)l_row[l], (uint32_t)l_ch[l]);
                cp16(sa, tp[l_tens[l]] + (size_t)l_row[l] * K + k0 + l_ch[l] * 8);
            }
            CP_COMMIT();
        }

        const uint32_t stb = sbase + (ks % 3) * STAGE_B;
        #pragma unroll
        for (int kk = 0; kk < 2; kk++) {          // two k16 halves of BK=32
            const uint32_t bchunk = (uint32_t)(kk * 2) + b_kbit;
            const uint32_t achunk = (uint32_t)(kk * 2) + a_kbit;
            uint32_t bh[4][2], bl[4][2];
            #pragma unroll
            for (int p = 0; p < 2; p++) {
                uint32_t brr = (uint32_t)(bn + p * 16 + b_rowlane);
                uint32_t boff = sw_off(brr, bchunk);
                uint32_t r4[4];
                ldsm_x4(r4, stb + 2 * TILE_B + boff);
                bh[2*p][0] = r4[0]; bh[2*p][1] = r4[1];
                bh[2*p+1][0] = r4[2]; bh[2*p+1][1] = r4[3];
                ldsm_x4(r4, stb + 3 * TILE_B + boff);
                bl[2*p][0] = r4[0]; bl[2*p][1] = r4[1];
                bl[2*p+1][0] = r4[2]; bl[2*p+1][1] = r4[3];
            }
            #pragma unroll
            for (int mt = 0; mt < 4; mt++) {
                uint32_t ah4[4], al4[4];
                uint32_t arr = (uint32_t)(warp_m * 64 + mt * 16 + (lane & 15));
                uint32_t aoff = sw_off(arr, achunk);
                ldsm_x4(ah4, stb + aoff);
                ldsm_x4(al4, stb + TILE_B + aoff);
                #pragma unroll
                for (int nt = 0; nt < 4; nt++) mma16816(acc[mt][nt], ah4, bh[nt]);
                #pragma unroll
                for (int nt = 0; nt < 4; nt++) mma16816(acc[mt][nt], ah4, bl[nt]);
                #pragma unroll
                for (int nt = 0; nt < 4; nt++) mma16816(acc[mt][nt], al4, bh[nt]);
            }
        }
    }

    // epilogue
    #pragma unroll
    for (int mt = 0; mt < 4; mt++) {
        const int row0 = brow * 128 + warp_m * 64 + mt * 16 + (lane >> 2);
        #pragma unroll
        for (int nt = 0; nt < 4; nt++) {
            const int col = bcol * 128 + warp_n * 32 + nt * 8 + (lane & 3) * 2;
            if (is_split) {
                // C pre-zeroed; two half-K CTAs accumulate (order-invariant)
                atomicAdd(C + (size_t)row0 * N + col,       acc[mt][nt][0]);
                atomicAdd(C + (size_t)row0 * N + col + 1,   acc[mt][nt][1]);
                atomicAdd(C + (size_t)(row0 + 8) * N + col,     acc[mt][nt][2]);
                atomicAdd(C + (size_t)(row0 + 8) * N + col + 1, acc[mt][nt][3]);
            } else {
                float b0 = 0.f, b1 = 0.f;
                if (bias) { b0 = __ldg(&bias[col]); b1 = __ldg(&bias[col + 1]); }
                *reinterpret_cast<float2*>(C + (size_t)row0 * N + col) =
                    make_float2(acc[mt][nt][0] + b0, acc[mt][nt][1] + b1);
                *reinterpret_cast<float2*>(C + (size_t)(row0 + 8) * N + col) =
                    make_float2(acc[mt][nt][2] + b0, acc[mt][nt][3] + b1);
            }
        }
    }
}

// ---------------------------------------------------------------------------
// Kernel 3: kv partials. grid = (64, KVPARTS) -> 512 CTAs (full-chip).
// ---------------------------------------------------------------------------
__global__ void __launch_bounds__(256) kv_part_kernel()
{
    const int bh = blockIdx.x;
    const int part = blockIdx.y;
    const int b = bh >> 4, h = bh & 15;
    __shared__ float sk[32][64];
    __shared__ float sv[32][64];
    __shared__ float rkn[32];
    const int t = threadIdx.x;
    const int j1_0 = (t >> 4) << 2;
    const int j2_0 = (t & 15) << 2;
    const int mbase = part * (NK / KVPARTS);
    const float* fk = g_f + (size_t)(ROWS_Q + b * NK + mbase) * DIMT + h * DH;
    const float* fv = g_f + (size_t)(ROWS_Q + ROWS_K + b * NK + mbase) * DIMT + h * DH;

    float acc[4][4];
    #pragma unroll
    for (int i = 0; i < 4; i++)
        #pragma unroll
        for (int j = 0; j < 4; j++) acc[i][j] = 0.f;

    for (int m0 = 0; m0 < NK / KVPARTS; m0 += 32) {
        #pragma unroll
        for (int l = 0; l < 2; l++) {
            int idx = t + l * 256;
            int r = idx >> 4, c = (idx & 15) << 2;
            float4 kv4 = *reinterpret_cast<const float4*>(&fk[(size_t)(m0 + r) * DIMT + c]);
            float4 vv4 = *reinterpret_cast<const float4*>(&fv[(size_t)(m0 + r) * DIMT + c]);
            *reinterpret_cast<float4*>(&sk[r][c]) = kv4;
            *reinterpret_cast<float4*>(&sv[r][c]) = vv4;
            float s = kv4.x*kv4.x + kv4.y*kv4.y + kv4.z*kv4.z + kv4.w*kv4.w;
            #pragma unroll
            for (int o = 8; o > 0; o >>= 1) s += __shfl_xor_sync(0xffffffffu, s, o);
            if ((t & 15) == 0) rkn[r] = rsqrtf(s);
        }
        __syncthreads();
        #pragma unroll 8
        for (int m = 0; m < 32; m++) {
            float rk = rkn[m];
            float4 a  = *reinterpret_cast<float4*>(&sk[m][j1_0]);
            float4 bq = *reinterpret_cast<float4*>(&sv[m][j2_0]);
            float a0 = a.x * rk, a1 = a.y * rk, a2 = a.z * rk, a3 = a.w * rk;
            acc[0][0] = fmaf(a0, bq.x, acc[0][0]); acc[0][1] = fmaf(a0, bq.y, acc[0][1]);
            acc[0][2] = fmaf(a0, bq.z, acc[0][2]); acc[0][3] = fmaf(a0, bq.w, acc[0][3]);
            acc[1][0] = fmaf(a1, bq.x, acc[1][0]); acc[1][1] = fmaf(a1, bq.y, acc[1][1]);
            acc[1][2] = fmaf(a1, bq.z, acc[1][2]); acc[1][3] = fmaf(a1, bq.w, acc[1][3]);
            acc[2][0] = fmaf(a2, bq.x, acc[2][0]); acc[2][1] = fmaf(a2, bq.y, acc[2][1]);
            acc[2][2] = fmaf(a2, bq.z, acc[2][2]); acc[2][3] = fmaf(a2, bq.w, acc[2][3]);
            acc[3][0] = fmaf(a3, bq.x, acc[3][0]); acc[3][1] = fmaf(a3, bq.y, acc[3][1]);
            acc[3][2] = fmaf(a3, bq.z, acc[3][2]); acc[3][3] = fmaf(a3, bq.w, acc[3][3]);
        }
        __syncthreads();
    }
    float* Sp = g_Sp + ((size_t)part * (BB * NH) + bh) * (DH * DH);
    #pragma unroll
    for (int i = 0; i < 4; i++)
        *reinterpret_cast<float4*>(&Sp[(j1_0 + i) * DH + j2_0]) =
            make_float4(acc[i][0], acc[i][1], acc[i][2], acc[i][3]);
}

// Reduce KVPARTS partials into g_S. grid=64, block=256; 4 float4 per thread.
__global__ void __launch_bounds__(256) s_reduce_kernel()
{
    const int bh = blockIdx.x;
    const int t = threadIdx.x;
    const size_t base = (size_t)bh * (DH * DH);
    #pragma unroll
    for (int l = 0; l < 4; l++) {
        int idx = t + l * 256;                       // 1024 float4s per matrix
        float4 s = make_float4(0.f, 0.f, 0.f, 0.f);
        #pragma unroll
        for (int p = 0; p < KVPARTS; p++) {
            float4 v = reinterpret_cast<const float4*>(
                g_Sp + ((size_t)p * (BB * NH)) * (DH * DH) + base)[idx];
            s.x += v.x; s.y += v.y; s.z += v.z; s.w += v.w;
        }
        reinterpret_cast<float4*>(g_S + base)[idx] = s;
    }
}

// ---------------------------------------------------------------------------
// Kernel 4: out_attn = (f_q/|f_q|) @ S[b,h]  -> bf16 hi/lo split, heads merged.
// ---------------------------------------------------------------------------
__global__ void __launch_bounds__(256) qs_kernel()
{
    const int bh = blockIdx.y;
    const int nt = blockIdx.x;
    const int b = bh >> 4, h = bh & 15;
    __shared__ float sS[64][64];
    __shared__ float sqT[64][64];
    __shared__ float rqn[64];
    const int t = threadIdx.x;

    const float* Sp = g_S + (size_t)bh * (DH * DH);
    #pragma unroll
    for (int l = 0; l < 4; l++) {
        int idx = t + l * 256;
        reinterpret_cast<float4*>(sS)[idx] = reinterpret_cast<const float4*>(Sp)[idx];
    }
    const float* fq = g_f + (size_t)(b * NQ + nt * 64) * DIMT + h * DH;
    #pragma unroll
    for (int l = 0; l < 4; l++) {
        int idx = t + l * 256;
        int r = idx >> 4, c = (idx & 15) << 2;
        float4 x = *reinterpret_cast<const float4*>(&fq[(size_t)r * DIMT + c]);
        sqT[c + 0][r] = x.x; sqT[c + 1][r] = x.y;
        sqT[c + 2][r] = x.z; sqT[c + 3][r] = x.w;
        float s = x.x*x.x + x.y*x.y + x.z*x.z + x.w*x.w;
        #pragma unroll
        for (int o = 8; o > 0; o >>= 1) s += __shfl_xor_sync(0xffffffffu, s, o);
        if ((t & 15) == 0) rqn[r] = rsqrtf(s);
    }
    __syncthreads();

    float acc[4][4];
    #pragma unroll
    for (int i = 0; i < 4; i++)
        #pragma unroll
        for (int j = 0; j < 4; j++) acc[i][j] = 0.f;
    const int r0 = (t >> 4) << 2, c0 = (t & 15) << 2;
    #pragma unroll 8
    for (int j1 = 0; j1 < 64; j1++) {
        float4 a  = *reinterpret_cast<float4*>(&sqT[j1][r0]);
        float4 bq = *reinterpret_cast<float4*>(&sS[j1][c0]);
        acc[0][0] = fmaf(a.x, bq.x, acc[0][0]); acc[0][1] = fmaf(a.x, bq.y, acc[0][1]);
        acc[0][2] = fmaf(a.x, bq.z, acc[0][2]); acc[0][3] = fmaf(a.x, bq.w, acc[0][3]);
        acc[1][0] = fmaf(a.y, bq.x, acc[1][0]); acc[1][1] = fmaf(a.y, bq.y, acc[1][1]);
        acc[1][2] = fmaf(a.y, bq.z, acc[1][2]); acc[1][3] = fmaf(a.y, bq.w, acc[1][3]);
        acc[2][0] = fmaf(a.z, bq.x, acc[2][0]); acc[2][1] = fmaf(a.z, bq.y, acc[2][1]);
        acc[2][2] = fmaf(a.z, bq.z, acc[2][2]); acc[2][3] = fmaf(a.z, bq.w, acc[2][3]);
        acc[3][0] = fmaf(a.w, bq.x, acc[3][0]); acc[3][1] = fmaf(a.w, bq.y, acc[3][1]);
        acc[3][2] = fmaf(a.w, bq.z, acc[3][2]); acc[3][3] = fmaf(a.w, bq.w, acc[3][3]);
    }
    const size_t obase = (size_t)(b * NQ + nt * 64 + r0) * DIMT + h * DH + c0;
    #pragma unroll
    for (int i = 0; i < 4; i++) {
        float rq = rqn[r0 + i];
        __nv_bfloat16 h0, h1, h2, h3, l0, l1, l2, l3;
        split2(acc[i][0] * rq, h0, l0); split2(acc[i][1] * rq, h1, l1);
        split2(acc[i][2] * rq, h2, l2); split2(acc[i][3] * rq, h3, l3);
        ushort4 uh = make_ushort4(__bfloat16_as_ushort(h0), __bfloat16_as_ushort(h1),
                                  __bfloat16_as_ushort(h2), __bfloat16_as_ushort(h3));
        ushort4 ul = make_ushort4(__bfloat16_as_ushort(l0), __bfloat16_as_ushort(l1),
                                  __bfloat16_as_ushort(l2), __bfloat16_as_ushort(l3));
        *reinterpret_cast<ushort4*>(g_oh + obase + (size_t)i * DIMT) = uh;
        *reinterpret_cast<ushort4*>(g_ol + obase + (size_t)i * DIMT) = ul;
    }
}

// ---------------------------------------------------------------------------
extern "C" void kernel_launch(void* const* d_in, const int* in_sizes, int n_in,
                              void* d_out, int out_size)
{
    const float* q     = (const float*)d_in[0];
    const float* k     = (const float*)d_in[1];
    const float* v     = (const float*)d_in[2];
    const float* gamma = (const float*)d_in[3];
    const float* beta  = (const float*)d_in[4];
    const float* W_in  = (const float*)d_in[5];
    const float* W_out = (const float*)d_in[6];
    const float* b_out = (const float*)d_in[7];
    float* out = (float*)d_out;

    __nv_bfloat16 *p_ah, *p_al, *p_oh, *p_ol, *p_wih, *p_wil, *p_woh, *p_wol;
    float *p_f;
    cudaGetSymbolAddress((void**)&p_ah,  g_ah);
    cudaGetSymbolAddress((void**)&p_al,  g_al);
    cudaGetSymbolAddress((void**)&p_oh,  g_oh);
    cudaGetSymbolAddress((void**)&p_ol,  g_ol);
    cudaGetSymbolAddress((void**)&p_wih, g_wih);
    cudaGetSymbolAddress((void**)&p_wil, g_wil);
    cudaGetSymbolAddress((void**)&p_woh, g_woh);
    cudaGetSymbolAddress((void**)&p_wol, g_wol);
    cudaGetSymbolAddress((void**)&p_f,   g_f);

    cudaFuncSetAttribute(gemm_mma_bf16x3,
                         cudaFuncAttributeMaxDynamicSharedMemorySize, GSMEM);

    // 1) LN + weight split + zero split-K region (one launch)
    prep_kernel<<<ROWS_TOT + 2048 + 1536, 256>>>(q, k, v, gamma, beta, W_in, W_out);
    // 2) projection GEMM: 1184 full-K tiles + 96 tiles as 192 half-K CTAs
    gemm_mma_bf16x3<<<G1_GRID, 256, GSMEM>>>(
        p_ah, p_al, p_wih, p_wil, p_f, ROWS_TOT, DIMT, DIMT, nullptr, G1_FULL);
    // 3) per-(b,h) S partials + reduce
    kv_part_kernel<<<dim3(BB * NH, KVPARTS), 256>>>();
    s_reduce_kernel<<<BB * NH, 256>>>();
    // 4) attn = q_hat @ S -> bf16 hi/lo
    qs_kernel<<<dim3(NQ / 64, BB * NH), 256>>>();
    // 5) output GEMM: 256 tiles, single wave, no split
    gemm_mma_bf16x3<<<256, 256, GSMEM>>>(
        p_oh, p_ol, p_woh, p_wol, out, ROWS_Q, DIMT, DIMT, b_out, 256);
}